// round 5
// baseline (speedup 1.0000x reference)
#include <cuda_runtime.h>
#include <cstdint>

#define NH     16
#define DH     64
#define LSEQ   1024
#define NB     4
#define DMODEL 1024
#define NPOS   257
#define BH     (NB*NH)       // 64
#define ROWS   (BH*LSEQ)     // 65536
#define MROW   (NB*LSEQ)     // 4096

// ---------------- scratch (device globals; no allocation allowed) ----------
__device__ float  g_Q[(size_t)ROWS*DH];       // [B,H,L,d]
__device__ float  g_K[(size_t)ROWS*DH];
__device__ float  g_V[(size_t)ROWS*DH];
__device__ float  g_R[(size_t)ROWS*NPOS];     // Q . posK^T
__device__ float  g_S[(size_t)ROWS*LSEQ];     // raw scores (268MB)
__device__ float2 g_stat[(size_t)ROWS*8];     // per (row, ktile): (max, sumexp)
__device__ float  g_O[(size_t)MROW*DMODEL];   // (O1+O2) in [B,L,D] layout

// ---------------- tf32 mma helpers -----------------------------------------
__device__ __forceinline__ unsigned f2tf(float f) {
    unsigned u;
    asm("cvt.rna.tf32.f32 %0, %1;" : "=r"(u) : "f"(f));
    return u;
}

__device__ __forceinline__ void mma_tf32(float* d, const unsigned* a, const unsigned* b) {
    asm volatile(
        "mma.sync.aligned.m16n8k8.row.col.f32.tf32.tf32.f32 "
        "{%0,%1,%2,%3}, {%4,%5,%6,%7}, {%8,%9}, {%0,%1,%2,%3};\n"
        : "+f"(d[0]), "+f"(d[1]), "+f"(d[2]), "+f"(d[3])
        : "r"(a[0]), "r"(a[1]), "r"(a[2]), "r"(a[3]), "r"(b[0]), "r"(b[1]));
}

// ========== merged QKV projection: C = x@W + b, head-major write ============
__global__ void __launch_bounds__(256) gemm_qkv(
    const float* __restrict__ A,
    const float* __restrict__ Wq, const float* __restrict__ bq,
    const float* __restrict__ Wk, const float* __restrict__ bk,
    const float* __restrict__ Wv, const float* __restrict__ bv)
{
    const int K = DMODEL, N = DMODEL;
    int zz = blockIdx.z;
    const float* W    = (zz == 0) ? Wq : (zz == 1) ? Wk : Wv;
    const float* bias = (zz == 0) ? bq : (zz == 1) ? bk : bv;
    float* C          = (zz == 0) ? g_Q : (zz == 1) ? g_K : g_V;

    __shared__ __align__(16) unsigned As[128][36];
    __shared__ __align__(16) unsigned Bs[32][136];
    int tid = threadIdx.x;
    int bm = blockIdx.y * 128, bn = blockIdx.x * 128;
    int warp = tid >> 5, lane = tid & 31;
    int wm = (warp >> 2) * 64, wn = (warp & 3) * 32;
    int g = lane >> 2, i4 = lane & 3;

    float acc[4][4][4] = {};
    int am = tid >> 3, ak = (tid & 7) * 4;
    int bk2 = tid >> 5, bn4 = (tid & 31) * 4;

    float4 ra[4], rw[4];
#pragma unroll
    for (int r = 0; r < 4; r++) {
        ra[r] = *(const float4*)&A[(size_t)(bm + am + 32 * r) * K + ak];
        rw[r] = *(const float4*)&W[(size_t)(bk2 + 8 * r) * N + bn + bn4];
    }

    for (int k0 = 0; k0 < K; k0 += 32) {
#pragma unroll
        for (int r = 0; r < 4; r++) {
            *(uint4*)&As[am + 32 * r][ak] =
                make_uint4(f2tf(ra[r].x), f2tf(ra[r].y), f2tf(ra[r].z), f2tf(ra[r].w));
            *(uint4*)&Bs[bk2 + 8 * r][bn4] =
                make_uint4(f2tf(rw[r].x), f2tf(rw[r].y), f2tf(rw[r].z), f2tf(rw[r].w));
        }
        __syncthreads();
        if (k0 + 32 < K) {
#pragma unroll
            for (int r = 0; r < 4; r++) {
                ra[r] = *(const float4*)&A[(size_t)(bm + am + 32 * r) * K + k0 + 32 + ak];
                rw[r] = *(const float4*)&W[(size_t)(k0 + 32 + bk2 + 8 * r) * N + bn + bn4];
            }
        }
#pragma unroll
        for (int ks = 0; ks < 32; ks += 8) {
            unsigned af[4][4], bf[4][2];
#pragma unroll
            for (int mi = 0; mi < 4; mi++) {
                int r0 = wm + 16 * mi + g;
                af[mi][0] = As[r0][ks + i4];
                af[mi][1] = As[r0 + 8][ks + i4];
                af[mi][2] = As[r0][ks + i4 + 4];
                af[mi][3] = As[r0 + 8][ks + i4 + 4];
            }
#pragma unroll
            for (int ni = 0; ni < 4; ni++) {
                bf[ni][0] = Bs[ks + i4][wn + 8 * ni + g];
                bf[ni][1] = Bs[ks + i4 + 4][wn + 8 * ni + g];
            }
#pragma unroll
            for (int mi = 0; mi < 4; mi++)
#pragma unroll
                for (int ni = 0; ni < 4; ni++)
                    mma_tf32(acc[mi][ni], af[mi], bf[ni]);
        }
        __syncthreads();
    }

#pragma unroll
    for (int mi = 0; mi < 4; mi++) {
#pragma unroll
        for (int ni = 0; ni < 4; ni++) {
#pragma unroll
            for (int e = 0; e < 4; e++) {
                int r = bm + wm + 16 * mi + g + (e >> 1) * 8;
                int c = bn + wn + 8 * ni + 2 * i4 + (e & 1);
                float v = acc[mi][ni][e] + bias[c];
                int b = r >> 10, l = r & 1023, h = c >> 6, dd = c & 63;
                C[(((size_t)(b * NH + h) * LSEQ + l) << 6) + dd] = v;
            }
        }
    }
}

// ============ out projection: out = g_O @ Wo + bo (row-major) ===============
__global__ void __launch_bounds__(256) gemm_out(
    const float* __restrict__ A, const float* __restrict__ W,
    const float* __restrict__ bias, float* __restrict__ C)
{
    const int K = DMODEL, N = DMODEL;
    __shared__ __align__(16) unsigned As[128][36];
    __shared__ __align__(16) unsigned Bs[32][136];
    int tid = threadIdx.x;
    int bm = blockIdx.y * 128, bn = blockIdx.x * 128;
    int warp = tid >> 5, lane = tid & 31;
    int wm = (warp >> 2) * 64, wn = (warp & 3) * 32;
    int g = lane >> 2, i4 = lane & 3;

    float acc[4][4][4] = {};
    int am = tid >> 3, ak = (tid & 7) * 4;
    int bk2 = tid >> 5, bn4 = (tid & 31) * 4;

    float4 ra[4], rw[4];
#pragma unroll
    for (int r = 0; r < 4; r++) {
        ra[r] = *(const float4*)&A[(size_t)(bm + am + 32 * r) * K + ak];
        rw[r] = *(const float4*)&W[(size_t)(bk2 + 8 * r) * N + bn + bn4];
    }

    for (int k0 = 0; k0 < K; k0 += 32) {
#pragma unroll
        for (int r = 0; r < 4; r++) {
            *(uint4*)&As[am + 32 * r][ak] =
                make_uint4(f2tf(ra[r].x), f2tf(ra[r].y), f2tf(ra[r].z), f2tf(ra[r].w));
            *(uint4*)&Bs[bk2 + 8 * r][bn4] =
                make_uint4(f2tf(rw[r].x), f2tf(rw[r].y), f2tf(rw[r].z), f2tf(rw[r].w));
        }
        __syncthreads();
        if (k0 + 32 < K) {
#pragma unroll
            for (int r = 0; r < 4; r++) {
                ra[r] = *(const float4*)&A[(size_t)(bm + am + 32 * r) * K + k0 + 32 + ak];
                rw[r] = *(const float4*)&W[(size_t)(k0 + 32 + bk2 + 8 * r) * N + bn + bn4];
            }
        }
#pragma unroll
        for (int ks = 0; ks < 32; ks += 8) {
            unsigned af[4][4], bf[4][2];
#pragma unroll
            for (int mi = 0; mi < 4; mi++) {
                int r0 = wm + 16 * mi + g;
                af[mi][0] = As[r0][ks + i4];
                af[mi][1] = As[r0 + 8][ks + i4];
                af[mi][2] = As[r0][ks + i4 + 4];
                af[mi][3] = As[r0 + 8][ks + i4 + 4];
            }
#pragma unroll
            for (int ni = 0; ni < 4; ni++) {
                bf[ni][0] = Bs[ks + i4][wn + 8 * ni + g];
                bf[ni][1] = Bs[ks + i4 + 4][wn + 8 * ni + g];
            }
#pragma unroll
            for (int mi = 0; mi < 4; mi++)
#pragma unroll
                for (int ni = 0; ni < 4; ni++)
                    mma_tf32(acc[mi][ni], af[mi], bf[ni]);
        }
        __syncthreads();
    }

#pragma unroll
    for (int mi = 0; mi < 4; mi++) {
#pragma unroll
        for (int ni = 0; ni < 4; ni++) {
#pragma unroll
            for (int e = 0; e < 4; e++) {
                int r = bm + wm + 16 * mi + g + (e >> 1) * 8;
                int c = bn + wn + 8 * ni + 2 * i4 + (e & 1);
                C[(size_t)r * N + c] = acc[mi][ni][e] + bias[c];
            }
        }
    }
}

// ======== R = Q @ posK^T (tf32 mma; M=65536, N=257->3x128, K=64) ===========
__global__ void __launch_bounds__(256) gemm_qposk_t(const float* __restrict__ posK)
{
    __shared__ __align__(16) unsigned As[128][36];
    __shared__ __align__(16) unsigned Bs[32][132];
    int tid = threadIdx.x;
    int bm = blockIdx.y * 128, bn = blockIdx.x * 128;
    int warp = tid >> 5, lane = tid & 31;
    int wm = (warp >> 2) * 64, wn = (warp & 3) * 32;
    int g = lane >> 2, i4 = lane & 3;

    float acc[4][4][4] = {};
    int am = tid >> 3, ak = (tid & 7) * 4;
    int nl = tid >> 3, k4 = (tid & 7) * 4;

    for (int k0 = 0; k0 < DH; k0 += 32) {
#pragma unroll
        for (int r = 0; r < 4; r++) {
            float4 v = *(const float4*)&g_Q[(size_t)(bm + am + 32 * r) * DH + k0 + ak];
            *(uint4*)&As[am + 32 * r][ak] =
                make_uint4(f2tf(v.x), f2tf(v.y), f2tf(v.z), f2tf(v.w));
            int n = bn + nl + 32 * r;
            float4 w = make_float4(0.f, 0.f, 0.f, 0.f);
            if (n < NPOS) w = *(const float4*)&posK[(size_t)n * DH + k0 + k4];
            Bs[k4 + 0][nl + 32 * r] = f2tf(w.x);
            Bs[k4 + 1][nl + 32 * r] = f2tf(w.y);
            Bs[k4 + 2][nl + 32 * r] = f2tf(w.z);
            Bs[k4 + 3][nl + 32 * r] = f2tf(w.w);
        }
        __syncthreads();
#pragma unroll
        for (int ks = 0; ks < 32; ks += 8) {
            unsigned af[4][4], bf[4][2];
#pragma unroll
            for (int mi = 0; mi < 4; mi++) {
                int r0 = wm + 16 * mi + g;
                af[mi][0] = As[r0][ks + i4];
                af[mi][1] = As[r0 + 8][ks + i4];
                af[mi][2] = As[r0][ks + i4 + 4];
                af[mi][3] = As[r0 + 8][ks + i4 + 4];
            }
#pragma unroll
            for (int ni = 0; ni < 4; ni++) {
                bf[ni][0] = Bs[ks + i4][wn + 8 * ni + g];
                bf[ni][1] = Bs[ks + i4 + 4][wn + 8 * ni + g];
            }
#pragma unroll
            for (int mi = 0; mi < 4; mi++)
#pragma unroll
                for (int ni = 0; ni < 4; ni++)
                    mma_tf32(acc[mi][ni], af[mi], bf[ni]);
        }
        __syncthreads();
    }

#pragma unroll
    for (int mi = 0; mi < 4; mi++) {
#pragma unroll
        for (int ni = 0; ni < 4; ni++) {
#pragma unroll
            for (int e = 0; e < 4; e++) {
                int r = bm + wm + 16 * mi + g + (e >> 1) * 8;
                int n = bn + wn + 8 * ni + 2 * i4 + (e & 1);
                if (n < NPOS) g_R[(size_t)r * NPOS + n] = acc[mi][ni][e];
            }
        }
    }
}

// ===== S = (Q K^T + gather(R)) * 0.125 * pad  +  per-tile softmax stats =====
__global__ void __launch_bounds__(256) attn_scores_t(const float* __restrict__ pad)
{
    __shared__ __align__(16) unsigned Qs[128][36];
    __shared__ __align__(16) unsigned Ks[128][36];
    int z = blockIdx.z;
    const float* Qp = g_Q + (size_t)z * LSEQ * DH;
    const float* Kp = g_K + (size_t)z * LSEQ * DH;
    int bm = blockIdx.y * 128, bn = blockIdx.x * 128;
    int tid = threadIdx.x;
    int warp = tid >> 5, lane = tid & 31;
    int wm = (warp >> 2) * 64, wn = (warp & 3) * 32;
    int g = lane >> 2, i4 = lane & 3;

    float acc[4][4][4] = {};
    int am = tid >> 3, ak = (tid & 7) * 4;

    for (int k0 = 0; k0 < DH; k0 += 32) {
#pragma unroll
        for (int r = 0; r < 4; r++) {
            float4 v = *(const float4*)&Qp[(size_t)(bm + am + 32 * r) * DH + k0 + ak];
            *(uint4*)&Qs[am + 32 * r][ak] =
                make_uint4(f2tf(v.x), f2tf(v.y), f2tf(v.z), f2tf(v.w));
            float4 w = *(const float4*)&Kp[(size_t)(bn + am + 32 * r) * DH + k0 + ak];
            *(uint4*)&Ks[am + 32 * r][ak] =
                make_uint4(f2tf(w.x), f2tf(w.y), f2tf(w.z), f2tf(w.w));
        }
        __syncthreads();
#pragma unroll
        for (int ks = 0; ks < 32; ks += 8) {
            unsigned af[4][4], bf[4][2];
#pragma unroll
            for (int mi = 0; mi < 4; mi++) {
                int r0 = wm + 16 * mi + g;
                af[mi][0] = Qs[r0][ks + i4];
                af[mi][1] = Qs[r0 + 8][ks + i4];
                af[mi][2] = Qs[r0][ks + i4 + 4];
                af[mi][3] = Qs[r0 + 8][ks + i4 + 4];
            }
#pragma unroll
            for (int ni = 0; ni < 4; ni++) {
                int n0 = wn + 8 * ni + g;
                bf[ni][0] = Ks[n0][ks + i4];
                bf[ni][1] = Ks[n0][ks + i4 + 4];
            }
#pragma unroll
            for (int mi = 0; mi < 4; mi++)
#pragma unroll
                for (int ni = 0; ni < 4; ni++)
                    mma_tf32(acc[mi][ni], af[mi], bf[ni]);
        }
        __syncthreads();
    }

    int b = z >> 4;
    int warp4 = warp & 3;
    float* smax = (float*)&Qs[0][0];   // 128*16
    float* ssum = smax + 2048;         // 128*16
    float* rowm = ssum + 2048;         // 128   (total 4224 <= 4608)

    // pass 1: write S, per-thread row max
#pragma unroll
    for (int mi = 0; mi < 4; mi++) {
#pragma unroll
        for (int e1 = 0; e1 < 2; e1++) {
            int rl = wm + 16 * mi + g + 8 * e1;
            int q = bm + rl;
            float mx = -3.0e38f;
#pragma unroll
            for (int ni = 0; ni < 4; ni++) {
#pragma unroll
                for (int e0 = 0; e0 < 2; e0++) {
                    int kp = bn + wn + 8 * ni + 2 * i4 + e0;
                    int dlt = min(max(kp - q, -128), 128);
                    float r2 = g_R[((size_t)z * LSEQ + q) * NPOS + dlt + 128];
                    float s = (acc[mi][ni][e1 * 2 + e0] + r2) * 0.125f * pad[b * LSEQ + kp];
                    g_S[((size_t)z * LSEQ + q) * LSEQ + kp] = s;
                    mx = fmaxf(mx, s);
                }
            }
            smax[rl * 16 + warp4 * 4 + i4] = mx;
        }
    }
    __syncthreads();
    if (tid < 128) {
        float m = smax[tid * 16];
#pragma unroll
        for (int j = 1; j < 16; j++) m = fmaxf(m, smax[tid * 16 + j]);
        rowm[tid] = m;
    }
    __syncthreads();
    // pass 2: sum of exp(s - rowmax)
#pragma unroll
    for (int mi = 0; mi < 4; mi++) {
#pragma unroll
        for (int e1 = 0; e1 < 2; e1++) {
            int rl = wm + 16 * mi + g + 8 * e1;
            int q = bm + rl;
            float m = rowm[rl];
            float se = 0.f;
#pragma unroll
            for (int ni = 0; ni < 4; ni++) {
#pragma unroll
                for (int e0 = 0; e0 < 2; e0++) {
                    int kp = bn + wn + 8 * ni + 2 * i4 + e0;
                    int dlt = min(max(kp - q, -128), 128);
                    float r2 = g_R[((size_t)z * LSEQ + q) * NPOS + dlt + 128];
                    float s = (acc[mi][ni][e1 * 2 + e0] + r2) * 0.125f * pad[b * LSEQ + kp];
                    se += __expf(s - m);
                }
            }
            ssum[rl * 16 + warp4 * 4 + i4] = se;
        }
    }
    __syncthreads();
    if (tid < 128) {
        float l = 0.f;
#pragma unroll
        for (int j = 0; j < 16; j++) l += ssum[tid * 16 + j];
        int q = bm + tid;
        g_stat[((size_t)z * LSEQ + q) * 8 + blockIdx.x] = make_float2(rowm[tid], l);
    }
}

// ===== fused: P = softmax(S) from stats; O = P@V + T@posV; T in smem ========
#define TSTRIDE 292
#define AVT_SMEM ((128*TSTRIDE + 128*36 + 32*72 + 256 + 2048)*4)

__global__ void __launch_bounds__(256) attn_avT(const float* __restrict__ posV)
{
    extern __shared__ __align__(16) char smdyn[];
    unsigned* Ts  = (unsigned*)smdyn;                 // 128*292 tf32 bins
    unsigned* Asm = Ts + 128 * TSTRIDE;               // 128*36 P tile
    unsigned* Bsm = Asm + 128 * 36;                   // 32*72  V / posV tile
    float*    rs  = (float*)(Bsm + 32 * 72);          // 128*2 (m, 1/l)
    float*    e0s = rs + 256;                         // 128*8 edge p<=0
    float*    e1s = e0s + 1024;                       // 128*8 edge p>=256

    int z = blockIdx.y;
    const float* S = g_S + (size_t)z * LSEQ * LSEQ;
    const float* V = g_V + (size_t)z * LSEQ * DH;
    int bm = blockIdx.x * 128;
    int tid = threadIdx.x;
    int warp = tid >> 5, lane = tid & 31;
    int wm = (warp >> 1) * 32, wn = (warp & 1) * 32;
    int g = lane >> 2, i4 = lane & 3;

    // zero T bins
    uint4 z4 = make_uint4(0, 0, 0, 0);
    for (int i = tid * 4; i < 128 * TSTRIDE; i += 1024) *(uint4*)&Ts[i] = z4;

    // combine per-tile stats -> (m, 1/l)
    if (tid < 128) {
        int q = bm + tid;
        const float2* st = &g_stat[((size_t)z * LSEQ + q) * 8];
        float m = st[0].x;
#pragma unroll
        for (int j = 1; j < 8; j++) m = fmaxf(m, st[j].x);
        float l = 0.f;
#pragma unroll
        for (int j = 0; j < 8; j++) l += st[j].y * __expf(st[j].x - m);
        rs[tid * 2] = m;
        rs[tid * 2 + 1] = 1.f / l;
    }
    __syncthreads();

    float acc[2][4][4] = {};
    int am = tid >> 3, ak = (tid & 7) * 4;
    int vk = tid >> 4, vn4 = (tid & 15) * 4;
    float te0[4] = {}, te1[4] = {};

    float4 ra[4], rv[2];
#pragma unroll
    for (int r = 0; r < 4; r++)
        ra[r] = *(const float4*)&S[(size_t)(bm + am + 32 * r) * LSEQ + ak];
#pragma unroll
    for (int r = 0; r < 2; r++)
        rv[r] = *(const float4*)&V[(size_t)(vk + 16 * r) * DH + vn4];

    for (int k0 = 0; k0 < LSEQ; k0 += 32) {
#pragma unroll
        for (int r = 0; r < 4; r++) {
            int rl = am + 32 * r;
            float m = rs[2 * rl], il = rs[2 * rl + 1];
            float p0 = __expf(ra[r].x - m) * il;
            float p1 = __expf(ra[r].y - m) * il;
            float p2 = __expf(ra[r].z - m) * il;
            float p3 = __expf(ra[r].w - m) * il;
            unsigned t0 = f2tf(p0), t1 = f2tf(p1), t2 = f2tf(p2), t3 = f2tf(p3);
            *(uint4*)&Asm[rl * 36 + ak] = make_uint4(t0, t1, t2, t3);
            int binb = k0 + ak - bm - rl + 128;   // bin of first element
            // element 0
            if (binb <= 0)        te0[r] += p0;
            else if (binb >= 256) te1[r] += p0;
            else                  Ts[rl * TSTRIDE + binb] = t0;
            if (binb + 1 <= 0)        te0[r] += p1;
            else if (binb + 1 >= 256) te1[r] += p1;
            else                      Ts[rl * TSTRIDE + binb + 1] = t1;
            if (binb + 2 <= 0)        te0[r] += p2;
            else if (binb + 2 >= 256) te1[r] += p2;
            else                      Ts[rl * TSTRIDE + binb + 2] = t2;
            if (binb + 3 <= 0)        te0[r] += p3;
            else if (binb + 3 >= 256) te1[r] += p3;
            else                      Ts[rl * TSTRIDE + binb + 3] = t3;
        }
#pragma unroll
        for (int r = 0; r < 2; r++)
            *(uint4*)&Bsm[(vk + 16 * r) * 72 + vn4] =
                make_uint4(f2tf(rv[r].x), f2tf(rv[r].y), f2tf(rv[r].z), f2tf(rv[r].w));
        __syncthreads();
        if (k0 + 32 < LSEQ) {
#pragma unroll
            for (int r = 0; r < 4; r++)
                ra[r] = *(const float4*)&S[(size_t)(bm + am + 32 * r) * LSEQ + k0 + 32 + ak];
#pragma unroll
            for (int r = 0; r < 2; r++)
                rv[r] = *(const float4*)&V[(size_t)(k0 + 32 + vk + 16 * r) * DH + vn4];
        }
#pragma unroll
        for (int ks = 0; ks < 32; ks += 8) {
            unsigned af[2][4], bf[4][2];
#pragma unroll
            for (int mi = 0; mi < 2; mi++) {
                int r0 = wm + 16 * mi + g;
                af[mi][0] = Asm[r0 * 36 + ks + i4];
                af[mi][1] = Asm[(r0 + 8) * 36 + ks + i4];
                af[mi][2] = Asm[r0 * 36 + ks + i4 + 4];
                af[mi][3] = Asm[(r0 + 8) * 36 + ks + i4 + 4];
            }
#pragma unroll
            for (int ni = 0; ni < 4; ni++) {
                bf[ni][0] = Bsm[(ks + i4) * 72 + wn + 8 * ni + g];
                bf[ni][1] = Bsm[(ks + i4 + 4) * 72 + wn + 8 * ni + g];
            }
#pragma unroll
            for (int mi = 0; mi < 2; mi++)
#pragma unroll
                for (int ni = 0; ni < 4; ni++)
                    mma_tf32(acc[mi][ni], af[mi], bf[ni]);
        }
        __syncthreads();
    }

    // reduce edge bins into Ts[.][0] and Ts[.][256]
#pragma unroll
    for (int r = 0; r < 4; r++) {
        e0s[(am + 32 * r) * 8 + (tid & 7)] = te0[r];
        e1s[(am + 32 * r) * 8 + (tid & 7)] = te1[r];
    }
    __syncthreads();
    if (tid < 128) {
        float s0 = 0.f, s1 = 0.f;
#pragma unroll
        for (int j = 0; j < 8; j++) { s0 += e0s[tid * 8 + j]; s1 += e1s[tid * 8 + j]; }
        Ts[tid * TSTRIDE + 0]   = f2tf(s0);
        Ts[tid * TSTRIDE + 256] = f2tf(s1);
    }
    __syncthreads();

    // O += T @ posV  (K = 288, 9 chunks of 32; cols 257..287 are zero)
    for (int c = 0; c < 9; c++) {
        int kc0 = c * 32;
#pragma unroll
        for (int r = 0; r < 2; r++) {
            int k = kc0 + vk + 16 * r;
            float4 w = make_float4(0.f, 0.f, 0.f, 0.f);
            if (k < NPOS) w = *(const float4*)&posV[(size_t)k * DH + vn4];
            *(uint4*)&Bsm[(vk + 16 * r) * 72 + vn4] =
                make_uint4(f2tf(w.x), f2tf(w.y), f2tf(w.z), f2tf(w.w));
        }
        __syncthreads();
#pragma unroll
        for (int ks = 0; ks < 32; ks += 8) {
            unsigned af[2][4], bf[4][2];
#pragma unroll
            for (int mi = 0; mi < 2; mi++) {
                int r0 = wm + 16 * mi + g;
                af[mi][0] = Ts[r0 * TSTRIDE + kc0 + ks + i4];
                af[mi][1] = Ts[(r0 + 8) * TSTRIDE + kc0 + ks + i4];
                af[mi][2] = Ts[r0 * TSTRIDE + kc0 + ks + i4 + 4];
                af[mi][3] = Ts[(r0 + 8) * TSTRIDE + kc0 + ks + i4 + 4];
            }
#pragma unroll
            for (int ni = 0; ni < 4; ni++) {
                bf[ni][0] = Bsm[(kc0 % 1 + ks + i4) * 72 + wn + 8 * ni + g];
                bf[ni][1] = Bsm[(ks + i4 + 4) * 72 + wn + 8 * ni + g];
            }
#pragma unroll
            for (int mi = 0; mi < 2; mi++)
#pragma unroll
                for (int ni = 0; ni < 4; ni++)
                    mma_tf32(acc[mi][ni], af[mi], bf[ni]);
        }
        __syncthreads();
    }

    int b = z >> 4, h = z & 15;
#pragma unroll
    for (int mi = 0; mi < 2; mi++) {
#pragma unroll
        for (int ni = 0; ni < 4; ni++) {
#pragma unroll
            for (int e = 0; e < 4; e++) {
                int q = bm + wm + 16 * mi + g + (e >> 1) * 8;
                int n = wn + 8 * ni + 2 * i4 + (e & 1);
                g_O[((size_t)(b * LSEQ + q)) * DMODEL + h * 64 + n] = acc[mi][ni][e];
            }
        }
    }
}

// ---------------------------------------------------------------------------
extern "C" void kernel_launch(void* const* d_in, const int* in_sizes, int n_in,
                              void* d_out, int out_size)
{
    const float* x    = (const float*)d_in[0];
    const float* pad  = (const float*)d_in[1];
    const float* Wq   = (const float*)d_in[2];
    const float* bq   = (const float*)d_in[3];
    const float* Wk   = (const float*)d_in[4];
    const float* bk   = (const float*)d_in[5];
    const float* Wv   = (const float*)d_in[6];
    const float* bv   = (const float*)d_in[7];
    const float* Wo   = (const float*)d_in[8];
    const float* bo   = (const float*)d_in[9];
    const float* posK = (const float*)d_in[10];
    const float* posV = (const float*)d_in[11];
    float* out = (float*)d_out;

    float* Op;
    cudaGetSymbolAddress((void**)&Op, g_O);

    cudaFuncSetAttribute(attn_avT, cudaFuncAttributeMaxDynamicSharedMemorySize, AVT_SMEM);

    gemm_qkv<<<dim3(DMODEL / 128, MROW / 128, 3), 256>>>(x, Wq, bq, Wk, bk, Wv, bv);
    gemm_qposk_t<<<dim3(3, ROWS / 128), 256>>>(posK);
    attn_scores_t<<<dim3(8, 8, BH), 256>>>(pad);
    attn_avT<<<dim3(8, BH), 256, AVT_SMEM>>>(posV);
    gemm_out<<<dim3(DMODEL / 128, MROW / 128), 256>>>(Op, Wo, bo, out);
}

// round 6
// speedup vs baseline: 1.0182x; 1.0182x over previous
#include <cuda_runtime.h>
#include <cstdint>

#define NH     16
#define DH     64
#define LSEQ   1024
#define NB     4
#define DMODEL 1024
#define NPOS   257
#define TP     288           // padded stride for T (9 k-chunks of 32)
#define BH     (NB*NH)       // 64
#define ROWS   (BH*LSEQ)     // 65536
#define MROW   (NB*LSEQ)     // 4096

// ---------------- scratch (device globals; no allocation allowed) ----------
__device__ float g_Q[(size_t)ROWS*DH];        // [B,H,L,d]
__device__ float g_K[(size_t)ROWS*DH];
__device__ float g_V[(size_t)ROWS*DH];
__device__ float g_R[(size_t)ROWS*NPOS];      // Q . posK^T
__device__ float g_T[(size_t)ROWS*TP];        // scattered A (padded stride)
__device__ float g_S[(size_t)ROWS*LSEQ];      // scores / attn probs (268MB)
__device__ float g_O[(size_t)MROW*DMODEL];    // (O1+O2) in [B,L,D] layout

// ---------------- tf32 mma helpers -----------------------------------------
__device__ __forceinline__ unsigned f2tf(float f) {
    unsigned u;
    asm("cvt.rna.tf32.f32 %0, %1;" : "=r"(u) : "f"(f));
    return u;
}

__device__ __forceinline__ void mma_tf32(float* d, const unsigned* a, const unsigned* b) {
    asm volatile(
        "mma.sync.aligned.m16n8k8.row.col.f32.tf32.tf32.f32 "
        "{%0,%1,%2,%3}, {%4,%5,%6,%7}, {%8,%9}, {%0,%1,%2,%3};\n"
        : "+f"(d[0]), "+f"(d[1]), "+f"(d[2]), "+f"(d[3])
        : "r"(a[0]), "r"(a[1]), "r"(a[2]), "r"(a[3]), "r"(b[0]), "r"(b[1]));
}

// ======= fragment-major big GEMM core (128x128 tile, K=N=1024) ==============
// Smem holds mma fragments directly:
//   A group (mtile 0..7, kstep 0..3): 132 words; lane's 4-reg a-frag contiguous.
//   B group (kstep 0..3, ntile 0..15): 66 words; lane's 2-reg b-frag contiguous.
template<bool HEADMAJOR>
__device__ __forceinline__ void gemm_core(
    const float* __restrict__ A, const float* __restrict__ W,
    const float* __restrict__ bias, float* __restrict__ C,
    unsigned* AsF, unsigned* BsF)
{
    const int K = DMODEL, N = DMODEL;
    int tid = threadIdx.x;
    int bm = blockIdx.y * 128, bn = blockIdx.x * 128;
    int warp = tid >> 5, lane = tid & 31;
    int wm4 = (warp >> 2) * 4;   // mtile base (16-row tiles)
    int wn4 = (warp & 3) * 4;    // ntile base (8-col tiles)
    int g = lane >> 2, i4 = lane & 3;

    float acc[4][4][4] = {};

    int am = tid >> 3, ak = (tid & 7) * 4;       // A loader: row am(+32r), k ak..ak+3
    int bk2 = tid >> 5, bn4 = (tid & 31) * 4;    // B loader: k bk2(+8r), n bn4..bn4+3

    // A store mapping: value (m, k) -> group (m>>4)*4 + (k>>3),
    //   word = G*132 + 16*(m&7) + 4*(k&3) + [(m>>3)&1] + 2*[(k>>2)&1]
    int a_g = am & 7;
    int a_reg = ((am >> 3) & 1) + 2 * ((ak >> 2) & 1);
    int a_kstep = ak >> 3;
    int a_mt0 = am >> 4;
    // B store mapping: value (k, n) -> group (k>>3)*16 + (n>>3),
    //   word = G*66 + 2*((n&7)*4 + (k&3)) + [(k>>2)&1]
    int b_nt = bn4 >> 3;
    int b_base0 = ((bn4 & 7) * 4 + (bk2 & 3)) * 2 + (bk2 >> 2);

    float4 ra[4], rw[4];
#pragma unroll
    for (int r = 0; r < 4; r++) {
        ra[r] = *(const float4*)&A[(size_t)(bm + am + 32 * r) * K + ak];
        rw[r] = *(const float4*)&W[(size_t)(bk2 + 8 * r) * N + bn + bn4];
    }

    for (int k0 = 0; k0 < K; k0 += 32) {
#pragma unroll
        for (int r = 0; r < 4; r++) {
            int base = ((a_mt0 + 2 * r) * 4 + a_kstep) * 132 + 16 * a_g + a_reg;
            AsF[base + 0]  = f2tf(ra[r].x);
            AsF[base + 4]  = f2tf(ra[r].y);
            AsF[base + 8]  = f2tf(ra[r].z);
            AsF[base + 12] = f2tf(ra[r].w);
            int baseb = (r * 16 + b_nt) * 66 + b_base0;
            BsF[baseb + 0]  = f2tf(rw[r].x);
            BsF[baseb + 8]  = f2tf(rw[r].y);
            BsF[baseb + 16] = f2tf(rw[r].z);
            BsF[baseb + 24] = f2tf(rw[r].w);
        }
        __syncthreads();
        if (k0 + 32 < K) {
#pragma unroll
            for (int r = 0; r < 4; r++) {
                ra[r] = *(const float4*)&A[(size_t)(bm + am + 32 * r) * K + k0 + 32 + ak];
                rw[r] = *(const float4*)&W[(size_t)(k0 + 32 + bk2 + 8 * r) * N + bn + bn4];
            }
        }
#pragma unroll
        for (int kstep = 0; kstep < 4; kstep++) {
            uint4 af[4]; uint2 bf[4];
#pragma unroll
            for (int mi = 0; mi < 4; mi++)
                af[mi] = *(uint4*)&AsF[((wm4 + mi) * 4 + kstep) * 132 + lane * 4];
#pragma unroll
            for (int ni = 0; ni < 4; ni++)
                bf[ni] = *(uint2*)&BsF[(kstep * 16 + wn4 + ni) * 66 + lane * 2];
#pragma unroll
            for (int mi = 0; mi < 4; mi++)
#pragma unroll
                for (int ni = 0; ni < 4; ni++)
                    mma_tf32(acc[mi][ni], (const unsigned*)&af[mi], (const unsigned*)&bf[ni]);
        }
        __syncthreads();
    }

    int wm = wm4 * 16, wn = wn4 * 8;
#pragma unroll
    for (int mi = 0; mi < 4; mi++) {
#pragma unroll
        for (int ni = 0; ni < 4; ni++) {
#pragma unroll
            for (int e = 0; e < 4; e++) {
                int r = bm + wm + 16 * mi + g + (e >> 1) * 8;
                int c = bn + wn + 8 * ni + 2 * i4 + (e & 1);
                float v = acc[mi][ni][e] + bias[c];
                if (HEADMAJOR) {
                    int b = r >> 10, l = r & 1023, h = c >> 6, dd = c & 63;
                    C[(((size_t)(b * NH + h) * LSEQ + l) << 6) + dd] = v;
                } else {
                    C[(size_t)r * DMODEL + c] = v;
                }
            }
        }
    }
}

// ========== merged QKV projection (z selects Q/K/V), head-major =============
__global__ void __launch_bounds__(256) gemm_qkv(
    const float* __restrict__ A,
    const float* __restrict__ Wq, const float* __restrict__ bq,
    const float* __restrict__ Wk, const float* __restrict__ bk,
    const float* __restrict__ Wv, const float* __restrict__ bv)
{
    __shared__ __align__(16) unsigned AsF[32 * 132];
    __shared__ __align__(16) unsigned BsF[64 * 66];
    int zz = blockIdx.z;
    const float* W    = (zz == 0) ? Wq : (zz == 1) ? Wk : Wv;
    const float* bias = (zz == 0) ? bq : (zz == 1) ? bk : bv;
    float* C          = (zz == 0) ? g_Q : (zz == 1) ? g_K : g_V;
    gemm_core<true>(A, W, bias, C, AsF, BsF);
}

// ============ out projection: out = g_O @ Wo + bo (row-major) ===============
__global__ void __launch_bounds__(256) gemm_out(
    const float* __restrict__ W, const float* __restrict__ bias,
    float* __restrict__ C)
{
    __shared__ __align__(16) unsigned AsF[32 * 132];
    __shared__ __align__(16) unsigned BsF[64 * 66];
    gemm_core<false>(g_O, W, bias, C, AsF, BsF);
}

// ======== R = Q @ posK^T (tf32 mma; M=65536, N=257->3x128, K=64) ===========
__global__ void __launch_bounds__(256) gemm_qposk_t(const float* __restrict__ posK)
{
    __shared__ __align__(16) unsigned As[128][36];
    __shared__ __align__(16) unsigned Bs[32][132];
    int tid = threadIdx.x;
    int bm = blockIdx.y * 128, bn = blockIdx.x * 128;
    int warp = tid >> 5, lane = tid & 31;
    int wm = (warp >> 2) * 64, wn = (warp & 3) * 32;
    int g = lane >> 2, i4 = lane & 3;

    float acc[4][4][4] = {};
    int am = tid >> 3, ak = (tid & 7) * 4;
    int nl = tid >> 3, k4 = (tid & 7) * 4;

    for (int k0 = 0; k0 < DH; k0 += 32) {
#pragma unroll
        for (int r = 0; r < 4; r++) {
            float4 v = *(const float4*)&g_Q[(size_t)(bm + am + 32 * r) * DH + k0 + ak];
            *(uint4*)&As[am + 32 * r][ak] =
                make_uint4(f2tf(v.x), f2tf(v.y), f2tf(v.z), f2tf(v.w));
            int n = bn + nl + 32 * r;
            float4 w = make_float4(0.f, 0.f, 0.f, 0.f);
            if (n < NPOS) w = *(const float4*)&posK[(size_t)n * DH + k0 + k4];
            Bs[k4 + 0][nl + 32 * r] = f2tf(w.x);
            Bs[k4 + 1][nl + 32 * r] = f2tf(w.y);
            Bs[k4 + 2][nl + 32 * r] = f2tf(w.z);
            Bs[k4 + 3][nl + 32 * r] = f2tf(w.w);
        }
        __syncthreads();
#pragma unroll
        for (int ks = 0; ks < 32; ks += 8) {
            unsigned af[4][4], bf[4][2];
#pragma unroll
            for (int mi = 0; mi < 4; mi++) {
                int r0 = wm + 16 * mi + g;
                af[mi][0] = As[r0][ks + i4];
                af[mi][1] = As[r0 + 8][ks + i4];
                af[mi][2] = As[r0][ks + i4 + 4];
                af[mi][3] = As[r0 + 8][ks + i4 + 4];
            }
#pragma unroll
            for (int ni = 0; ni < 4; ni++) {
                bf[ni][0] = Bs[ks + i4][wn + 8 * ni + g];
                bf[ni][1] = Bs[ks + i4 + 4][wn + 8 * ni + g];
            }
#pragma unroll
            for (int mi = 0; mi < 4; mi++)
#pragma unroll
                for (int ni = 0; ni < 4; ni++)
                    mma_tf32(acc[mi][ni], af[mi], bf[ni]);
        }
        __syncthreads();
    }

#pragma unroll
    for (int mi = 0; mi < 4; mi++) {
#pragma unroll
        for (int ni = 0; ni < 4; ni++) {
#pragma unroll
            for (int e = 0; e < 4; e++) {
                int r = bm + wm + 16 * mi + g + (e >> 1) * 8;
                int n = bn + wn + 8 * ni + 2 * i4 + (e & 1);
                if (n < NPOS) g_R[(size_t)r * NPOS + n] = acc[mi][ni][e];
            }
        }
    }
}

// ===== S = (Q K^T + gather(R)) * 0.125 * pad, tf32 mma, batched over bh =====
__global__ void __launch_bounds__(256) attn_scores_t(const float* __restrict__ pad)
{
    __shared__ __align__(16) unsigned Qs[128][36];
    __shared__ __align__(16) unsigned Ks[128][36];
    int z = blockIdx.z;
    const float* Qp = g_Q + (size_t)z * LSEQ * DH;
    const float* Kp = g_K + (size_t)z * LSEQ * DH;
    int bm = blockIdx.y * 128, bn = blockIdx.x * 128;
    int tid = threadIdx.x;
    int warp = tid >> 5, lane = tid & 31;
    int wm = (warp >> 2) * 64, wn = (warp & 3) * 32;
    int g = lane >> 2, i4 = lane & 3;

    float acc[4][4][4] = {};
    int am = tid >> 3, ak = (tid & 7) * 4;

    for (int k0 = 0; k0 < DH; k0 += 32) {
#pragma unroll
        for (int r = 0; r < 4; r++) {
            float4 v = *(const float4*)&Qp[(size_t)(bm + am + 32 * r) * DH + k0 + ak];
            *(uint4*)&Qs[am + 32 * r][ak] =
                make_uint4(f2tf(v.x), f2tf(v.y), f2tf(v.z), f2tf(v.w));
            float4 w = *(const float4*)&Kp[(size_t)(bn + am + 32 * r) * DH + k0 + ak];
            *(uint4*)&Ks[am + 32 * r][ak] =
                make_uint4(f2tf(w.x), f2tf(w.y), f2tf(w.z), f2tf(w.w));
        }
        __syncthreads();
#pragma unroll
        for (int ks = 0; ks < 32; ks += 8) {
            unsigned af[4][4], bf[4][2];
#pragma unroll
            for (int mi = 0; mi < 4; mi++) {
                int r0 = wm + 16 * mi + g;
                af[mi][0] = Qs[r0][ks + i4];
                af[mi][1] = Qs[r0 + 8][ks + i4];
                af[mi][2] = Qs[r0][ks + i4 + 4];
                af[mi][3] = Qs[r0 + 8][ks + i4 + 4];
            }
#pragma unroll
            for (int ni = 0; ni < 4; ni++) {
                int n0 = wn + 8 * ni + g;
                bf[ni][0] = Ks[n0][ks + i4];
                bf[ni][1] = Ks[n0][ks + i4 + 4];
            }
#pragma unroll
            for (int mi = 0; mi < 4; mi++)
#pragma unroll
                for (int ni = 0; ni < 4; ni++)
                    mma_tf32(acc[mi][ni], af[mi], bf[ni]);
        }
        __syncthreads();
    }

    int b = z >> 4;
#pragma unroll
    for (int mi = 0; mi < 4; mi++) {
#pragma unroll
        for (int ni = 0; ni < 4; ni++) {
#pragma unroll
            for (int e = 0; e < 4; e++) {
                int q = bm + wm + 16 * mi + g + (e >> 1) * 8;
                int kp = bn + wn + 8 * ni + 2 * i4 + (e & 1);
                int dlt = min(max(kp - q, -128), 128);
                float r2 = g_R[((size_t)z * LSEQ + q) * NPOS + dlt + 128];
                g_S[((size_t)z * LSEQ + q) * LSEQ + kp] =
                    (acc[mi][ni][e] + r2) * 0.125f * pad[b * LSEQ + kp];
            }
        }
    }
}

// ====== fused softmax (in-place on g_S) + T scatter (padded stride) ========
__global__ void __launch_bounds__(256) softmax_T()
{
    int row = blockIdx.x;
    int q = row & 1023;
    float* S = g_S + (size_t)row * LSEQ;
    float* T = g_T + (size_t)row * TP;
    int tid = threadIdx.x;
    __shared__ float sA[1024];
    __shared__ float red[256];
    __shared__ float r0s[256], r1s[256];

    float4 v = *(float4*)&S[tid * 4];
    float m = fmaxf(fmaxf(v.x, v.y), fmaxf(v.z, v.w));
    red[tid] = m; __syncthreads();
    for (int s = 128; s > 0; s >>= 1) {
        if (tid < s) red[tid] = fmaxf(red[tid], red[tid + s]);
        __syncthreads();
    }
    m = red[0]; __syncthreads();
    v.x = __expf(v.x - m); v.y = __expf(v.y - m);
    v.z = __expf(v.z - m); v.w = __expf(v.w - m);
    red[tid] = v.x + v.y + v.z + v.w; __syncthreads();
    for (int s = 128; s > 0; s >>= 1) {
        if (tid < s) red[tid] += red[tid + s];
        __syncthreads();
    }
    float inv = 1.f / red[0];
    v.x *= inv; v.y *= inv; v.z *= inv; v.w *= inv;
    *(float4*)&S[tid * 4] = v;
    *(float4*)&sA[tid * 4] = v;
    __syncthreads();

    if (tid < 255) {                 // middle bins p=1..255 : exactly one k
        int p = tid + 1;
        int k = q + p - 128;
        T[p] = (k >= 0 && k < 1024) ? sA[k] : 0.f;
    }
    float s0 = 0.f;                  // p=0 : k <= q-128
    for (int k = tid; k <= q - 128; k += 256) s0 += sA[k];
    float s1 = 0.f;                  // p=256 : k >= q+128
    for (int k = q + 128 + tid; k < 1024; k += 256) s1 += sA[k];
    r0s[tid] = s0; r1s[tid] = s1; __syncthreads();
    for (int s = 128; s > 0; s >>= 1) {
        if (tid < s) { r0s[tid] += r0s[tid + s]; r1s[tid] += r1s[tid + s]; }
        __syncthreads();
    }
    if (tid == 0) { T[0] = r0s[0]; T[256] = r1s[0]; }
    if (tid < TP - NPOS) T[NPOS + tid] = 0.f;   // zero pad 257..287
}

// =========== O1 = A @ V (tf32 mma, prefetched), write permuted =============
__global__ void __launch_bounds__(256) gemm_av_t()
{
    __shared__ __align__(16) unsigned As[128][36];
    __shared__ __align__(16) unsigned Bs[32][72];
    int z = blockIdx.y;
    const float* A = g_S + (size_t)z * LSEQ * LSEQ;
    const float* V = g_V + (size_t)z * LSEQ * DH;
    int bm = blockIdx.x * 128;
    int tid = threadIdx.x;
    int warp = tid >> 5, lane = tid & 31;
    int wm = (warp >> 1) * 32, wn = (warp & 1) * 32;
    int g = lane >> 2, i4 = lane & 3;

    float acc[2][4][4] = {};
    int am = tid >> 3, ak = (tid & 7) * 4;
    int vk = tid >> 4, vn4 = (tid & 15) * 4;

    float4 ra[4], rv[2];
#pragma unroll
    for (int r = 0; r < 4; r++)
        ra[r] = *(const float4*)&A[(size_t)(bm + am + 32 * r) * LSEQ + ak];
#pragma unroll
    for (int r = 0; r < 2; r++)
        rv[r] = *(const float4*)&V[(size_t)(vk + 16 * r) * DH + vn4];

    for (int k0 = 0; k0 < LSEQ; k0 += 32) {
#pragma unroll
        for (int r = 0; r < 4; r++)
            *(uint4*)&As[am + 32 * r][ak] =
                make_uint4(f2tf(ra[r].x), f2tf(ra[r].y), f2tf(ra[r].z), f2tf(ra[r].w));
#pragma unroll
        for (int r = 0; r < 2; r++)
            *(uint4*)&Bs[vk + 16 * r][vn4] =
                make_uint4(f2tf(rv[r].x), f2tf(rv[r].y), f2tf(rv[r].z), f2tf(rv[r].w));
        __syncthreads();
        if (k0 + 32 < LSEQ) {
#pragma unroll
            for (int r = 0; r < 4; r++)
                ra[r] = *(const float4*)&A[(size_t)(bm + am + 32 * r) * LSEQ + k0 + 32 + ak];
#pragma unroll
            for (int r = 0; r < 2; r++)
                rv[r] = *(const float4*)&V[(size_t)(k0 + 32 + vk + 16 * r) * DH + vn4];
        }
#pragma unroll
        for (int ks = 0; ks < 32; ks += 8) {
            unsigned af[2][4], bf[4][2];
#pragma unroll
            for (int mi = 0; mi < 2; mi++) {
                int r0 = wm + 16 * mi + g;
                af[mi][0] = As[r0][ks + i4];
                af[mi][1] = As[r0 + 8][ks + i4];
                af[mi][2] = As[r0][ks + i4 + 4];
                af[mi][3] = As[r0 + 8][ks + i4 + 4];
            }
#pragma unroll
            for (int ni = 0; ni < 4; ni++) {
                bf[ni][0] = Bs[ks + i4][wn + 8 * ni + g];
                bf[ni][1] = Bs[ks + i4 + 4][wn + 8 * ni + g];
            }
#pragma unroll
            for (int mi = 0; mi < 2; mi++)
#pragma unroll
                for (int ni = 0; ni < 4; ni++)
                    mma_tf32(acc[mi][ni], af[mi], bf[ni]);
        }
        __syncthreads();
    }

    int b = z >> 4, h = z & 15;
#pragma unroll
    for (int mi = 0; mi < 2; mi++) {
#pragma unroll
        for (int ni = 0; ni < 4; ni++) {
#pragma unroll
            for (int e = 0; e < 4; e++) {
                int q = bm + wm + 16 * mi + g + (e >> 1) * 8;
                int n = wn + 8 * ni + 2 * i4 + (e & 1);
                g_O[((size_t)(b * LSEQ + q)) * DMODEL + h * 64 + n] = acc[mi][ni][e];
            }
        }
    }
}

// ====== g_O += T @ posV (tf32 mma; M=65536, N=64, K=288 padded) ============
__global__ void __launch_bounds__(256) gemm_tposv_t(const float* __restrict__ posV)
{
    __shared__ __align__(16) unsigned As[128][36];
    __shared__ __align__(16) unsigned Bs[32][72];
    int bm = blockIdx.x * 128;
    int tid = threadIdx.x;
    int warp = tid >> 5, lane = tid & 31;
    int wm = warp * 16;
    int g = lane >> 2, i4 = lane & 3;

    float acc[8][4] = {};
    int am = tid >> 3, ak = (tid & 7) * 4;
    int vk = tid >> 4, vn4 = (tid & 15) * 4;

    for (int k0 = 0; k0 < TP; k0 += 32) {
#pragma unroll
        for (int r = 0; r < 4; r++) {
            float4 v = *(const float4*)&g_T[(size_t)(bm + am + 32 * r) * TP + k0 + ak];
            *(uint4*)&As[am + 32 * r][ak] =
                make_uint4(f2tf(v.x), f2tf(v.y), f2tf(v.z), f2tf(v.w));
        }
#pragma unroll
        for (int r = 0; r < 2; r++) {
            int k = k0 + vk + 16 * r;
            float4 w = make_float4(0.f, 0.f, 0.f, 0.f);
            if (k < NPOS) w = *(const float4*)&posV[(size_t)k * DH + vn4];
            *(uint4*)&Bs[vk + 16 * r][vn4] =
                make_uint4(f2tf(w.x), f2tf(w.y), f2tf(w.z), f2tf(w.w));
        }
        __syncthreads();
#pragma unroll
        for (int ks = 0; ks < 32; ks += 8) {
            unsigned af[4], bf[8][2];
            int r0 = wm + g;
            af[0] = As[r0][ks + i4];
            af[1] = As[r0 + 8][ks + i4];
            af[2] = As[r0][ks + i4 + 4];
            af[3] = As[r0 + 8][ks + i4 + 4];
#pragma unroll
            for (int ni = 0; ni < 8; ni++) {
                bf[ni][0] = Bs[ks + i4][8 * ni + g];
                bf[ni][1] = Bs[ks + i4 + 4][8 * ni + g];
            }
#pragma unroll
            for (int ni = 0; ni < 8; ni++)
                mma_tf32(acc[ni], af, bf[ni]);
        }
        __syncthreads();
    }

#pragma unroll
    for (int ni = 0; ni < 8; ni++) {
#pragma unroll
        for (int e = 0; e < 4; e++) {
            int r = bm + wm + g + (e >> 1) * 8;
            int z = r >> 10, q = r & 1023;
            int b = z >> 4, h = z & 15;
            int n = 8 * ni + 2 * i4 + (e & 1);
            size_t idx = ((size_t)(b * LSEQ + q)) * DMODEL + h * 64 + n;
            g_O[idx] += acc[ni][e];
        }
    }
}

// ---------------------------------------------------------------------------
extern "C" void kernel_launch(void* const* d_in, const int* in_sizes, int n_in,
                              void* d_out, int out_size)
{
    const float* x    = (const float*)d_in[0];
    const float* pad  = (const float*)d_in[1];
    const float* Wq   = (const float*)d_in[2];
    const float* bq   = (const float*)d_in[3];
    const float* Wk   = (const float*)d_in[4];
    const float* bk   = (const float*)d_in[5];
    const float* Wv   = (const float*)d_in[6];
    const float* bv   = (const float*)d_in[7];
    const float* Wo   = (const float*)d_in[8];
    const float* bo   = (const float*)d_in[9];
    const float* posK = (const float*)d_in[10];
    const float* posV = (const float*)d_in[11];
    float* out = (float*)d_out;

    gemm_qkv<<<dim3(DMODEL / 128, MROW / 128, 3), 256>>>(x, Wq, bq, Wk, bk, Wv, bv);
    gemm_qposk_t<<<dim3(3, ROWS / 128), 256>>>(posK);
    attn_scores_t<<<dim3(8, 8, BH), 256>>>(pad);
    softmax_T<<<ROWS, 256>>>();
    gemm_av_t<<<dim3(8, BH), 256>>>();
    gemm_tposv_t<<<dim3(ROWS / 128), 256>>>(posV);
    gemm_out<<<dim3(DMODEL / 128, MROW / 128), 256>>>(Wo, bo, out);
}

// round 7
// speedup vs baseline: 1.2412x; 1.2190x over previous
#include <cuda_runtime.h>
#include <cstdint>

#define NH     16
#define DH     64
#define LSEQ   1024
#define NB     4
#define DMODEL 1024
#define NPOS   257
#define TP     288           // padded stride for T (9 k-chunks of 32)
#define BH     (NB*NH)       // 64
#define ROWS   (BH*LSEQ)     // 65536
#define MROW   (NB*LSEQ)     // 4096

// ---------------- scratch (device globals; no allocation allowed) ----------
__device__ float  g_Q[(size_t)ROWS*DH];       // [B,H,L,d]
__device__ float  g_K[(size_t)ROWS*DH];
__device__ float  g_V[(size_t)ROWS*DH];
__device__ float  g_R[(size_t)ROWS*NPOS];     // Q . posK^T
__device__ float  g_T[(size_t)ROWS*TP];       // scattered probs (padded stride)
__device__ float  g_S[(size_t)ROWS*LSEQ];     // RAW scores (268MB)
__device__ float2 g_stat[(size_t)ROWS*8];     // per (row, ktile): (max, sumexp)
__device__ float2 g_stat2[(size_t)ROWS];      // per row: (max, 1/l)
__device__ float  g_O[(size_t)MROW*DMODEL];   // (O1+O2) in [B,L,D] layout

// ---------------- tf32 mma helpers -----------------------------------------
__device__ __forceinline__ unsigned f2tf(float f) {
    unsigned u;
    asm("cvt.rna.tf32.f32 %0, %1;" : "=r"(u) : "f"(f));
    return u;
}

__device__ __forceinline__ void mma_tf32(float* d, const unsigned* a, const unsigned* b) {
    asm volatile(
        "mma.sync.aligned.m16n8k8.row.col.f32.tf32.tf32.f32 "
        "{%0,%1,%2,%3}, {%4,%5,%6,%7}, {%8,%9}, {%0,%1,%2,%3};\n"
        : "+f"(d[0]), "+f"(d[1]), "+f"(d[2]), "+f"(d[3])
        : "r"(a[0]), "r"(a[1]), "r"(a[2]), "r"(a[3]), "r"(b[0]), "r"(b[1]));
}

// ======= big GEMM core (R3-proven layout, 128x128 tile, prefetched) =========
template<bool HEADMAJOR>
__device__ __forceinline__ void gemm_core(
    const float* __restrict__ A, const float* __restrict__ W,
    const float* __restrict__ bias, float* __restrict__ C)
{
    const int K = DMODEL, N = DMODEL;
    __shared__ __align__(16) unsigned As[128][36];
    __shared__ __align__(16) unsigned Bs[32][136];
    int tid = threadIdx.x;
    int bm = blockIdx.y * 128, bn = blockIdx.x * 128;
    int warp = tid >> 5, lane = tid & 31;
    int wm = (warp >> 2) * 64, wn = (warp & 3) * 32;
    int g = lane >> 2, i4 = lane & 3;

    float acc[4][4][4] = {};
    int am = tid >> 3, ak = (tid & 7) * 4;
    int bk2 = tid >> 5, bn4 = (tid & 31) * 4;

    float4 ra[4], rw[4];
#pragma unroll
    for (int r = 0; r < 4; r++) {
        ra[r] = *(const float4*)&A[(size_t)(bm + am + 32 * r) * K + ak];
        rw[r] = *(const float4*)&W[(size_t)(bk2 + 8 * r) * N + bn + bn4];
    }

    for (int k0 = 0; k0 < K; k0 += 32) {
#pragma unroll
        for (int r = 0; r < 4; r++) {
            *(uint4*)&As[am + 32 * r][ak] =
                make_uint4(f2tf(ra[r].x), f2tf(ra[r].y), f2tf(ra[r].z), f2tf(ra[r].w));
            *(uint4*)&Bs[bk2 + 8 * r][bn4] =
                make_uint4(f2tf(rw[r].x), f2tf(rw[r].y), f2tf(rw[r].z), f2tf(rw[r].w));
        }
        __syncthreads();
        if (k0 + 32 < K) {
#pragma unroll
            for (int r = 0; r < 4; r++) {
                ra[r] = *(const float4*)&A[(size_t)(bm + am + 32 * r) * K + k0 + 32 + ak];
                rw[r] = *(const float4*)&W[(size_t)(k0 + 32 + bk2 + 8 * r) * N + bn + bn4];
            }
        }
#pragma unroll
        for (int ks = 0; ks < 32; ks += 8) {
            unsigned af[4][4], bf[4][2];
#pragma unroll
            for (int mi = 0; mi < 4; mi++) {
                int r0 = wm + 16 * mi + g;
                af[mi][0] = As[r0][ks + i4];
                af[mi][1] = As[r0 + 8][ks + i4];
                af[mi][2] = As[r0][ks + i4 + 4];
                af[mi][3] = As[r0 + 8][ks + i4 + 4];
            }
#pragma unroll
            for (int ni = 0; ni < 4; ni++) {
                bf[ni][0] = Bs[ks + i4][wn + 8 * ni + g];
                bf[ni][1] = Bs[ks + i4 + 4][wn + 8 * ni + g];
            }
#pragma unroll
            for (int mi = 0; mi < 4; mi++)
#pragma unroll
                for (int ni = 0; ni < 4; ni++)
                    mma_tf32(acc[mi][ni], af[mi], bf[ni]);
        }
        __syncthreads();
    }

#pragma unroll
    for (int mi = 0; mi < 4; mi++) {
#pragma unroll
        for (int ni = 0; ni < 4; ni++) {
#pragma unroll
            for (int e = 0; e < 4; e++) {
                int r = bm + wm + 16 * mi + g + (e >> 1) * 8;
                int c = bn + wn + 8 * ni + 2 * i4 + (e & 1);
                float v = acc[mi][ni][e] + bias[c];
                if (HEADMAJOR) {
                    int b = r >> 10, l = r & 1023, h = c >> 6, dd = c & 63;
                    C[(((size_t)(b * NH + h) * LSEQ + l) << 6) + dd] = v;
                } else {
                    C[(size_t)r * DMODEL + c] = v;
                }
            }
        }
    }
}

// ========== merged QKV projection (z selects Q/K/V), head-major =============
__global__ void __launch_bounds__(256) gemm_qkv(
    const float* __restrict__ A,
    const float* __restrict__ Wq, const float* __restrict__ bq,
    const float* __restrict__ Wk, const float* __restrict__ bk,
    const float* __restrict__ Wv, const float* __restrict__ bv)
{
    int zz = blockIdx.z;
    const float* W    = (zz == 0) ? Wq : (zz == 1) ? Wk : Wv;
    const float* bias = (zz == 0) ? bq : (zz == 1) ? bk : bv;
    float* C          = (zz == 0) ? g_Q : (zz == 1) ? g_K : g_V;
    gemm_core<true>(A, W, bias, C);
}

// ============ out projection: out = g_O @ Wo + bo (row-major) ===============
__global__ void __launch_bounds__(256) gemm_out(
    const float* __restrict__ W, const float* __restrict__ bias,
    float* __restrict__ C)
{
    gemm_core<false>(g_O, W, bias, C);
}

// ======== R = Q @ posK^T (tf32 mma; M=65536, N=257->3x128, K=64) ===========
__global__ void __launch_bounds__(256) gemm_qposk_t(const float* __restrict__ posK)
{
    __shared__ __align__(16) unsigned As[128][36];
    __shared__ __align__(16) unsigned Bs[32][132];
    int tid = threadIdx.x;
    int bm = blockIdx.y * 128, bn = blockIdx.x * 128;
    int warp = tid >> 5, lane = tid & 31;
    int wm = (warp >> 2) * 64, wn = (warp & 3) * 32;
    int g = lane >> 2, i4 = lane & 3;

    float acc[4][4][4] = {};
    int am = tid >> 3, ak = (tid & 7) * 4;
    int nl = tid >> 3, k4 = (tid & 7) * 4;

    for (int k0 = 0; k0 < DH; k0 += 32) {
#pragma unroll
        for (int r = 0; r < 4; r++) {
            float4 v = *(const float4*)&g_Q[(size_t)(bm + am + 32 * r) * DH + k0 + ak];
            *(uint4*)&As[am + 32 * r][ak] =
                make_uint4(f2tf(v.x), f2tf(v.y), f2tf(v.z), f2tf(v.w));
            int n = bn + nl + 32 * r;
            float4 w = make_float4(0.f, 0.f, 0.f, 0.f);
            if (n < NPOS) w = *(const float4*)&posK[(size_t)n * DH + k0 + k4];
            Bs[k4 + 0][nl + 32 * r] = f2tf(w.x);
            Bs[k4 + 1][nl + 32 * r] = f2tf(w.y);
            Bs[k4 + 2][nl + 32 * r] = f2tf(w.z);
            Bs[k4 + 3][nl + 32 * r] = f2tf(w.w);
        }
        __syncthreads();
#pragma unroll
        for (int ks = 0; ks < 32; ks += 8) {
            unsigned af[4][4], bf[4][2];
#pragma unroll
            for (int mi = 0; mi < 4; mi++) {
                int r0 = wm + 16 * mi + g;
                af[mi][0] = As[r0][ks + i4];
                af[mi][1] = As[r0 + 8][ks + i4];
                af[mi][2] = As[r0][ks + i4 + 4];
                af[mi][3] = As[r0 + 8][ks + i4 + 4];
            }
#pragma unroll
            for (int ni = 0; ni < 4; ni++) {
                bf[ni][0] = Bs[ks + i4][wn + 8 * ni + g];
                bf[ni][1] = Bs[ks + i4 + 4][wn + 8 * ni + g];
            }
#pragma unroll
            for (int mi = 0; mi < 4; mi++)
#pragma unroll
                for (int ni = 0; ni < 4; ni++)
                    mma_tf32(acc[mi][ni], af[mi], bf[ni]);
        }
        __syncthreads();
    }

#pragma unroll
    for (int mi = 0; mi < 4; mi++) {
#pragma unroll
        for (int ni = 0; ni < 4; ni++) {
#pragma unroll
            for (int e = 0; e < 4; e++) {
                int r = bm + wm + 16 * mi + g + (e >> 1) * 8;
                int n = bn + wn + 8 * ni + 2 * i4 + (e & 1);
                if (n < NPOS) g_R[(size_t)r * NPOS + n] = acc[mi][ni][e];
            }
        }
    }
}

// ===== S = (Q K^T + gather(R)) * 0.125 * pad  +  per-tile softmax stats =====
__global__ void __launch_bounds__(256) attn_scores_t(const float* __restrict__ pad)
{
    __shared__ __align__(16) unsigned Qs[128][36];
    __shared__ __align__(16) unsigned Ks[128][36];
    int z = blockIdx.z;
    const float* Qp = g_Q + (size_t)z * LSEQ * DH;
    const float* Kp = g_K + (size_t)z * LSEQ * DH;
    int bm = blockIdx.y * 128, bn = blockIdx.x * 128;
    int tid = threadIdx.x;
    int warp = tid >> 5, lane = tid & 31;
    int wm = (warp >> 2) * 64, wn = (warp & 3) * 32;
    int g = lane >> 2, i4 = lane & 3;

    float acc[4][4][4] = {};
    int am = tid >> 3, ak = (tid & 7) * 4;

    for (int k0 = 0; k0 < DH; k0 += 32) {
#pragma unroll
        for (int r = 0; r < 4; r++) {
            float4 v = *(const float4*)&Qp[(size_t)(bm + am + 32 * r) * DH + k0 + ak];
            *(uint4*)&Qs[am + 32 * r][ak] =
                make_uint4(f2tf(v.x), f2tf(v.y), f2tf(v.z), f2tf(v.w));
            float4 w = *(const float4*)&Kp[(size_t)(bn + am + 32 * r) * DH + k0 + ak];
            *(uint4*)&Ks[am + 32 * r][ak] =
                make_uint4(f2tf(w.x), f2tf(w.y), f2tf(w.z), f2tf(w.w));
        }
        __syncthreads();
#pragma unroll
        for (int ks = 0; ks < 32; ks += 8) {
            unsigned af[4][4], bf[4][2];
#pragma unroll
            for (int mi = 0; mi < 4; mi++) {
                int r0 = wm + 16 * mi + g;
                af[mi][0] = Qs[r0][ks + i4];
                af[mi][1] = Qs[r0 + 8][ks + i4];
                af[mi][2] = Qs[r0][ks + i4 + 4];
                af[mi][3] = Qs[r0 + 8][ks + i4 + 4];
            }
#pragma unroll
            for (int ni = 0; ni < 4; ni++) {
                int n0 = wn + 8 * ni + g;
                bf[ni][0] = Ks[n0][ks + i4];
                bf[ni][1] = Ks[n0][ks + i4 + 4];
            }
#pragma unroll
            for (int mi = 0; mi < 4; mi++)
#pragma unroll
                for (int ni = 0; ni < 4; ni++)
                    mma_tf32(acc[mi][ni], af[mi], bf[ni]);
        }
        __syncthreads();
    }

    int b = z >> 4;
    int warp4 = warp & 3;
    float* smax = (float*)&Qs[0][0];   // 128*16
    float* ssum = smax + 2048;         // 128*16
    float* rowm = ssum + 2048;         // 128   (4224 floats <= 4608 avail)

    // pass 1: write raw S, per-thread row max
#pragma unroll
    for (int mi = 0; mi < 4; mi++) {
#pragma unroll
        for (int e1 = 0; e1 < 2; e1++) {
            int rl = wm + 16 * mi + g + 8 * e1;
            int q = bm + rl;
            float mx = -3.0e38f;
#pragma unroll
            for (int ni = 0; ni < 4; ni++) {
#pragma unroll
                for (int e0 = 0; e0 < 2; e0++) {
                    int kp = bn + wn + 8 * ni + 2 * i4 + e0;
                    int dlt = min(max(kp - q, -128), 128);
                    float r2 = g_R[((size_t)z * LSEQ + q) * NPOS + dlt + 128];
                    float s = (acc[mi][ni][e1 * 2 + e0] + r2) * 0.125f * pad[b * LSEQ + kp];
                    g_S[((size_t)z * LSEQ + q) * LSEQ + kp] = s;
                    acc[mi][ni][e1 * 2 + e0] = s;   // keep final score in regs
                    mx = fmaxf(mx, s);
                }
            }
            smax[rl * 16 + warp4 * 4 + i4] = mx;
        }
    }
    __syncthreads();
    if (tid < 128) {
        float m = smax[tid * 16];
#pragma unroll
        for (int j = 1; j < 16; j++) m = fmaxf(m, smax[tid * 16 + j]);
        rowm[tid] = m;
    }
    __syncthreads();
    // pass 2: sum of exp(s - rowmax) from registers
#pragma unroll
    for (int mi = 0; mi < 4; mi++) {
#pragma unroll
        for (int e1 = 0; e1 < 2; e1++) {
            int rl = wm + 16 * mi + g + 8 * e1;
            float m = rowm[rl];
            float se = 0.f;
#pragma unroll
            for (int ni = 0; ni < 4; ni++)
#pragma unroll
                for (int e0 = 0; e0 < 2; e0++)
                    se += __expf(acc[mi][ni][e1 * 2 + e0] - m);
            ssum[rl * 16 + warp4 * 4 + i4] = se;
        }
    }
    __syncthreads();
    if (tid < 128) {
        float l = 0.f;
#pragma unroll
        for (int j = 0; j < 16; j++) l += ssum[tid * 16 + j];
        int q = bm + tid;
        g_stat[((size_t)z * LSEQ + q) * 8 + blockIdx.x] = make_float2(rowm[tid], l);
    }
}

// ====== combine per-tile stats -> per-row (max, 1/l) ========================
__global__ void __launch_bounds__(256) combine_stats()
{
    int row = blockIdx.x * 256 + threadIdx.x;
    const float2* st = &g_stat[(size_t)row * 8];
    float m = st[0].x;
#pragma unroll
    for (int j = 1; j < 8; j++) m = fmaxf(m, st[j].x);
    float l = 0.f;
#pragma unroll
    for (int j = 0; j < 8; j++) l += st[j].y * __expf(st[j].x - m);
    g_stat2[row] = make_float2(m, 1.f / l);
}

// ====== stats_T: p = exp(s-m)*il from raw S; write T only (no S rewrite) ====
__global__ void __launch_bounds__(256) stats_T()
{
    int row = blockIdx.x;
    int q = row & 1023;
    const float* S = g_S + (size_t)row * LSEQ;
    float* T = g_T + (size_t)row * TP;
    int tid = threadIdx.x;
    int warp = tid >> 5, lane = tid & 31;
    __shared__ float sA[1024];
    __shared__ float r0s[8], r1s[8];

    float2 st = g_stat2[row];
    float m = st.x, il = st.y;

    float4 v = *(const float4*)&S[tid * 4];
    float p0 = __expf(v.x - m) * il;
    float p1 = __expf(v.y - m) * il;
    float p2 = __expf(v.z - m) * il;
    float p3 = __expf(v.w - m) * il;
    *(float4*)&sA[tid * 4] = make_float4(p0, p1, p2, p3);

    // edge partial sums (k <= q-128 -> s0 ; k >= q+128 -> s1)
    float s0 = 0.f, s1 = 0.f;
    int kb = tid * 4;
    int lo = q - 128, hi = q + 128;
    if (kb + 0 <= lo) s0 += p0; else if (kb + 0 >= hi) s1 += p0;
    if (kb + 1 <= lo) s0 += p1; else if (kb + 1 >= hi) s1 += p1;
    if (kb + 2 <= lo) s0 += p2; else if (kb + 2 >= hi) s1 += p2;
    if (kb + 3 <= lo) s0 += p3; else if (kb + 3 >= hi) s1 += p3;
#pragma unroll
    for (int off = 16; off > 0; off >>= 1) {
        s0 += __shfl_xor_sync(0xffffffffu, s0, off);
        s1 += __shfl_xor_sync(0xffffffffu, s1, off);
    }
    if (lane == 0) { r0s[warp] = s0; r1s[warp] = s1; }
    __syncthreads();

    if (tid < 255) {                 // middle bins p=1..255 : exactly one k
        int p = tid + 1;
        int k = q + p - 128;
        T[p] = (k >= 0 && k < 1024) ? sA[k] : 0.f;
    }
    if (tid == 0) {
        float a0 = 0.f, a1 = 0.f;
#pragma unroll
        for (int j = 0; j < 8; j++) { a0 += r0s[j]; a1 += r1s[j]; }
        T[0] = a0; T[256] = a1;
    }
    if (tid >= 225 && tid < 225 + (TP - NPOS)) T[NPOS + (tid - 225)] = 0.f;
}

// ====== O1 = P @ V : P computed on the fly from raw S + stats ===============
__global__ void __launch_bounds__(256) gemm_av_t()
{
    __shared__ __align__(16) unsigned As[128][36];
    __shared__ __align__(16) unsigned Bs[32][72];
    __shared__ float rs[256];        // (m, il) per row of the 128-row tile
    int z = blockIdx.y;
    const float* S = g_S + (size_t)z * LSEQ * LSEQ;
    const float* V = g_V + (size_t)z * LSEQ * DH;
    int bm = blockIdx.x * 128;
    int tid = threadIdx.x;
    int warp = tid >> 5, lane = tid & 31;
    int wm = (warp >> 1) * 32, wn = (warp & 1) * 32;
    int g = lane >> 2, i4 = lane & 3;

    if (tid < 128) {
        float2 st = g_stat2[(size_t)z * LSEQ + bm + tid];
        rs[tid * 2] = st.x;
        rs[tid * 2 + 1] = st.y;
    }
    __syncthreads();

    float acc[2][4][4] = {};
    int am = tid >> 3, ak = (tid & 7) * 4;
    int vk = tid >> 4, vn4 = (tid & 15) * 4;

    float4 ra[4], rv[2];
#pragma unroll
    for (int r = 0; r < 4; r++)
        ra[r] = *(const float4*)&S[(size_t)(bm + am + 32 * r) * LSEQ + ak];
#pragma unroll
    for (int r = 0; r < 2; r++)
        rv[r] = *(const float4*)&V[(size_t)(vk + 16 * r) * DH + vn4];

    for (int k0 = 0; k0 < LSEQ; k0 += 32) {
#pragma unroll
        for (int r = 0; r < 4; r++) {
            int rl = am + 32 * r;
            float m = rs[2 * rl], il = rs[2 * rl + 1];
            *(uint4*)&As[rl][ak] = make_uint4(
                f2tf(__expf(ra[r].x - m) * il),
                f2tf(__expf(ra[r].y - m) * il),
                f2tf(__expf(ra[r].z - m) * il),
                f2tf(__expf(ra[r].w - m) * il));
        }
#pragma unroll
        for (int r = 0; r < 2; r++)
            *(uint4*)&Bs[vk + 16 * r][vn4] =
                make_uint4(f2tf(rv[r].x), f2tf(rv[r].y), f2tf(rv[r].z), f2tf(rv[r].w));
        __syncthreads();
        if (k0 + 32 < LSEQ) {
#pragma unroll
            for (int r = 0; r < 4; r++)
                ra[r] = *(const float4*)&S[(size_t)(bm + am + 32 * r) * LSEQ + k0 + 32 + ak];
#pragma unroll
            for (int r = 0; r < 2; r++)
                rv[r] = *(const float4*)&V[(size_t)(k0 + 32 + vk + 16 * r) * DH + vn4];
        }
#pragma unroll
        for (int ks = 0; ks < 32; ks += 8) {
            unsigned af[2][4], bf[4][2];
#pragma unroll
            for (int mi = 0; mi < 2; mi++) {
                int r0 = wm + 16 * mi + g;
                af[mi][0] = As[r0][ks + i4];
                af[mi][1] = As[r0 + 8][ks + i4];
                af[mi][2] = As[r0][ks + i4 + 4];
                af[mi][3] = As[r0 + 8][ks + i4 + 4];
            }
#pragma unroll
            for (int ni = 0; ni < 4; ni++) {
                bf[ni][0] = Bs[ks + i4][wn + 8 * ni + g];
                bf[ni][1] = Bs[ks + i4 + 4][wn + 8 * ni + g];
            }
#pragma unroll
            for (int mi = 0; mi < 2; mi++)
#pragma unroll
                for (int ni = 0; ni < 4; ni++)
                    mma_tf32(acc[mi][ni], af[mi], bf[ni]);
        }
        __syncthreads();
    }

    int b = z >> 4, h = z & 15;
#pragma unroll
    for (int mi = 0; mi < 2; mi++) {
#pragma unroll
        for (int ni = 0; ni < 4; ni++) {
#pragma unroll
            for (int e = 0; e < 4; e++) {
                int q = bm + wm + 16 * mi + g + (e >> 1) * 8;
                int n = wn + 8 * ni + 2 * i4 + (e & 1);
                g_O[((size_t)(b * LSEQ + q)) * DMODEL + h * 64 + n] = acc[mi][ni][e];
            }
        }
    }
}

// ====== g_O += T @ posV (tf32 mma; M=65536, N=64, K=288 padded) ============
__global__ void __launch_bounds__(256) gemm_tposv_t(const float* __restrict__ posV)
{
    __shared__ __align__(16) unsigned As[128][36];
    __shared__ __align__(16) unsigned Bs[32][72];
    int bm = blockIdx.x * 128;
    int tid = threadIdx.x;
    int warp = tid >> 5, lane = tid & 31;
    int wm = warp * 16;
    int g = lane >> 2, i4 = lane & 3;

    float acc[8][4] = {};
    int am = tid >> 3, ak = (tid & 7) * 4;
    int vk = tid >> 4, vn4 = (tid & 15) * 4;

    for (int k0 = 0; k0 < TP; k0 += 32) {
#pragma unroll
        for (int r = 0; r < 4; r++) {
            float4 v = *(const float4*)&g_T[(size_t)(bm + am + 32 * r) * TP + k0 + ak];
            *(uint4*)&As[am + 32 * r][ak] =
                make_uint4(f2tf(v.x), f2tf(v.y), f2tf(v.z), f2tf(v.w));
        }
#pragma unroll
        for (int r = 0; r < 2; r++) {
            int k = k0 + vk + 16 * r;
            float4 w = make_float4(0.f, 0.f, 0.f, 0.f);
            if (k < NPOS) w = *(const float4*)&posV[(size_t)k * DH + vn4];
            *(uint4*)&Bs[vk + 16 * r][vn4] =
                make_uint4(f2tf(w.x), f2tf(w.y), f2tf(w.z), f2tf(w.w));
        }
        __syncthreads();
#pragma unroll
        for (int ks = 0; ks < 32; ks += 8) {
            unsigned af[4], bf[8][2];
            int r0 = wm + g;
            af[0] = As[r0][ks + i4];
            af[1] = As[r0 + 8][ks + i4];
            af[2] = As[r0][ks + i4 + 4];
            af[3] = As[r0 + 8][ks + i4 + 4];
#pragma unroll
            for (int ni = 0; ni < 8; ni++) {
                bf[ni][0] = Bs[ks + i4][8 * ni + g];
                bf[ni][1] = Bs[ks + i4 + 4][8 * ni + g];
            }
#pragma unroll
            for (int ni = 0; ni < 8; ni++)
                mma_tf32(acc[ni], af, bf[ni]);
        }
        __syncthreads();
    }

#pragma unroll
    for (int ni = 0; ni < 8; ni++) {
#pragma unroll
        for (int e = 0; e < 4; e++) {
            int r = bm + wm + g + (e >> 1) * 8;
            int z = r >> 10, q = r & 1023;
            int b = z >> 4, h = z & 15;
            int n = 8 * ni + 2 * i4 + (e & 1);
            size_t idx = ((size_t)(b * LSEQ + q)) * DMODEL + h * 64 + n;
            g_O[idx] += acc[ni][e];
        }
    }
}

// ---------------------------------------------------------------------------
extern "C" void kernel_launch(void* const* d_in, const int* in_sizes, int n_in,
                              void* d_out, int out_size)
{
    const float* x    = (const float*)d_in[0];
    const float* pad  = (const float*)d_in[1];
    const float* Wq   = (const float*)d_in[2];
    const float* bq   = (const float*)d_in[3];
    const float* Wk   = (const float*)d_in[4];
    const float* bk   = (const float*)d_in[5];
    const float* Wv   = (const float*)d_in[6];
    const float* bv   = (const float*)d_in[7];
    const float* Wo   = (const float*)d_in[8];
    const float* bo   = (const float*)d_in[9];
    const float* posK = (const float*)d_in[10];
    const float* posV = (const float*)d_in[11];
    float* out = (float*)d_out;

    gemm_qkv<<<dim3(DMODEL / 128, MROW / 128, 3), 256>>>(x, Wq, bq, Wk, bk, Wv, bv);
    gemm_qposk_t<<<dim3(3, ROWS / 128), 256>>>(posK);
    attn_scores_t<<<dim3(8, 8, BH), 256>>>(pad);
    combine_stats<<<ROWS / 256, 256>>>();
    stats_T<<<ROWS, 256>>>();
    gemm_av_t<<<dim3(8, BH), 256>>>();
    gemm_tposv_t<<<dim3(ROWS / 128), 256>>>(posV);
    gemm_out<<<dim3(DMODEL / 128, MROW / 128), 256>>>(Wo, bo, out);
}

// round 10
// speedup vs baseline: 1.3007x; 1.0479x over previous
#include <cuda_runtime.h>
#include <cstdint>

#define NH     16
#define DH     64
#define LSEQ   1024
#define NB     4
#define DMODEL 1024
#define NPOS   257
#define TP     288           // padded stride for T (9 k-chunks of 32)
#define BH     (NB*NH)       // 64
#define ROWS   (BH*LSEQ)     // 65536
#define MROW   (NB*LSEQ)     // 4096

// ---------------- scratch (device globals; no allocation allowed) ----------
__device__ float  g_Q[(size_t)ROWS*DH];       // [B,H,L,d]
__device__ float  g_K[(size_t)ROWS*DH];
__device__ float  g_V[(size_t)ROWS*DH];
__device__ float  g_R[(size_t)ROWS*NPOS];     // Q . posK^T
__device__ float  g_T[(size_t)ROWS*TP];       // scattered probs (padded stride)
__device__ float  g_S[(size_t)ROWS*LSEQ];     // RAW scores (268MB)
__device__ float2 g_stat[(size_t)ROWS*8];     // per (row, ktile): (max, sumexp)
__device__ float2 g_stat2[(size_t)ROWS];      // per row: (max, 1/l)
__device__ float  g_O[(size_t)MROW*DMODEL];   // (O1+O2) in [B,L,D] layout

// ---------------- tf32 mma helpers -----------------------------------------
__device__ __forceinline__ unsigned f2tf(float f) {
    unsigned u;
    asm("cvt.rna.tf32.f32 %0, %1;" : "=r"(u) : "f"(f));
    return u;
}

__device__ __forceinline__ void mma_tf32(float* d, const unsigned* a, const unsigned* b) {
    asm volatile(
        "mma.sync.aligned.m16n8k8.row.col.f32.tf32.tf32.f32 "
        "{%0,%1,%2,%3}, {%4,%5,%6,%7}, {%8,%9}, {%0,%1,%2,%3};\n"
        : "+f"(d[0]), "+f"(d[1]), "+f"(d[2]), "+f"(d[3])
        : "r"(a[0]), "r"(a[1]), "r"(a[2]), "r"(a[3]), "r"(b[0]), "r"(b[1]));
}

__device__ __forceinline__ void ldsm_x4(unsigned* r, uint32_t addr) {
    asm volatile("ldmatrix.sync.aligned.m8n8.x4.shared.b16 {%0,%1,%2,%3}, [%4];"
        : "=r"(r[0]), "=r"(r[1]), "=r"(r[2]), "=r"(r[3]) : "r"(addr));
}

// ======= big GEMM core (128x128 tile, prefetched, ldmatrix A-frags) =========
template<bool HEADMAJOR>
__device__ __forceinline__ void gemm_core(
    const float* __restrict__ A, const float* __restrict__ W,
    const float* __restrict__ bias, float* __restrict__ C)
{
    const int K = DMODEL, N = DMODEL;
    __shared__ __align__(16) unsigned As[128][36];
    __shared__ __align__(16) unsigned Bs[32][136];
    int tid = threadIdx.x;
    int bm = blockIdx.y * 128, bn = blockIdx.x * 128;
    int warp = tid >> 5, lane = tid & 31;
    int wm = (warp >> 2) * 64, wn = (warp & 3) * 32;
    int g = lane >> 2, i4 = lane & 3;

    // ldmatrix x4 per-lane source: blks (m0k0, m8k0, m0k4, m8k4)
    int lrow = (lane & 7) + 8 * ((lane >> 3) & 1);
    int lcol = 4 * (lane >> 4);
    uint32_t a_base = (uint32_t)__cvta_generic_to_shared(&As[0][0]);

    float acc[4][4][4] = {};
    int am = tid >> 3, ak = (tid & 7) * 4;
    int bk2 = tid >> 5, bn4 = (tid & 31) * 4;

    float4 ra[4], rw[4];
#pragma unroll
    for (int r = 0; r < 4; r++) {
        ra[r] = *(const float4*)&A[(size_t)(bm + am + 32 * r) * K + ak];
        rw[r] = *(const float4*)&W[(size_t)(bk2 + 8 * r) * N + bn + bn4];
    }

    for (int k0 = 0; k0 < K; k0 += 32) {
#pragma unroll
        for (int r = 0; r < 4; r++) {
            *(uint4*)&As[am + 32 * r][ak] =
                make_uint4(f2tf(ra[r].x), f2tf(ra[r].y), f2tf(ra[r].z), f2tf(ra[r].w));
            *(uint4*)&Bs[bk2 + 8 * r][bn4] =
                make_uint4(f2tf(rw[r].x), f2tf(rw[r].y), f2tf(rw[r].z), f2tf(rw[r].w));
        }
        __syncthreads();
        if (k0 + 32 < K) {
#pragma unroll
            for (int r = 0; r < 4; r++) {
                ra[r] = *(const float4*)&A[(size_t)(bm + am + 32 * r) * K + k0 + 32 + ak];
                rw[r] = *(const float4*)&W[(size_t)(k0 + 32 + bk2 + 8 * r) * N + bn + bn4];
            }
        }
#pragma unroll
        for (int ks = 0; ks < 32; ks += 8) {
            unsigned af[4][4], bf[4][2];
#pragma unroll
            for (int mi = 0; mi < 4; mi++)
                ldsm_x4(af[mi],
                    a_base + ((wm + 16 * mi + lrow) * 36 + ks + lcol) * 4);
#pragma unroll
            for (int ni = 0; ni < 4; ni++) {
                bf[ni][0] = Bs[ks + i4][wn + 8 * ni + g];
                bf[ni][1] = Bs[ks + i4 + 4][wn + 8 * ni + g];
            }
#pragma unroll
            for (int mi = 0; mi < 4; mi++)
#pragma unroll
                for (int ni = 0; ni < 4; ni++)
                    mma_tf32(acc[mi][ni], af[mi], bf[ni]);
        }
        __syncthreads();
    }

#pragma unroll
    for (int mi = 0; mi < 4; mi++) {
#pragma unroll
        for (int ni = 0; ni < 4; ni++) {
#pragma unroll
            for (int e = 0; e < 4; e++) {
                int r = bm + wm + 16 * mi + g + (e >> 1) * 8;
                int c = bn + wn + 8 * ni + 2 * i4 + (e & 1);
                float v = acc[mi][ni][e] + bias[c];
                if (HEADMAJOR) {
                    int b = r >> 10, l = r & 1023, h = c >> 6, dd = c & 63;
                    C[(((size_t)(b * NH + h) * LSEQ + l) << 6) + dd] = v;
                } else {
                    C[(size_t)r * DMODEL + c] = v;
                }
            }
        }
    }
}

// ========== merged QKV projection (z selects Q/K/V), head-major =============
__global__ void __launch_bounds__(256) gemm_qkv(
    const float* __restrict__ A,
    const float* __restrict__ Wq, const float* __restrict__ bq,
    const float* __restrict__ Wk, const float* __restrict__ bk,
    const float* __restrict__ Wv, const float* __restrict__ bv)
{
    int zz = blockIdx.z;
    const float* W    = (zz == 0) ? Wq : (zz == 1) ? Wk : Wv;
    const float* bias = (zz == 0) ? bq : (zz == 1) ? bk : bv;
    float* C          = (zz == 0) ? g_Q : (zz == 1) ? g_K : g_V;
    gemm_core<true>(A, W, bias, C);
}

// ============ out projection: out = g_O @ Wo + bo (row-major) ===============
__global__ void __launch_bounds__(256) gemm_out(
    const float* __restrict__ W, const float* __restrict__ bias,
    float* __restrict__ C)
{
    gemm_core<false>(g_O, W, bias, C);
}

// ======== R = Q @ posK^T (tf32 mma; M=65536, N=257->3x128, K=64) ===========
__global__ void __launch_bounds__(256) gemm_qposk_t(const float* __restrict__ posK)
{
    __shared__ __align__(16) unsigned As[128][36];
    __shared__ __align__(16) unsigned Bs[32][132];
    int tid = threadIdx.x;
    int bm = blockIdx.y * 128, bn = blockIdx.x * 128;
    int warp = tid >> 5, lane = tid & 31;
    int wm = (warp >> 2) * 64, wn = (warp & 3) * 32;
    int g = lane >> 2, i4 = lane & 3;

    int lrow = (lane & 7) + 8 * ((lane >> 3) & 1);
    int lcol = 4 * (lane >> 4);
    uint32_t a_base = (uint32_t)__cvta_generic_to_shared(&As[0][0]);

    float acc[4][4][4] = {};
    int am = tid >> 3, ak = (tid & 7) * 4;
    int nl = tid >> 3, k4 = (tid & 7) * 4;

    for (int k0 = 0; k0 < DH; k0 += 32) {
#pragma unroll
        for (int r = 0; r < 4; r++) {
            float4 v = *(const float4*)&g_Q[(size_t)(bm + am + 32 * r) * DH + k0 + ak];
            *(uint4*)&As[am + 32 * r][ak] =
                make_uint4(f2tf(v.x), f2tf(v.y), f2tf(v.z), f2tf(v.w));
            int n = bn + nl + 32 * r;
            float4 w = make_float4(0.f, 0.f, 0.f, 0.f);
            if (n < NPOS) w = *(const float4*)&posK[(size_t)n * DH + k0 + k4];
            Bs[k4 + 0][nl + 32 * r] = f2tf(w.x);
            Bs[k4 + 1][nl + 32 * r] = f2tf(w.y);
            Bs[k4 + 2][nl + 32 * r] = f2tf(w.z);
            Bs[k4 + 3][nl + 32 * r] = f2tf(w.w);
        }
        __syncthreads();
#pragma unroll
        for (int ks = 0; ks < 32; ks += 8) {
            unsigned af[4][4], bf[4][2];
#pragma unroll
            for (int mi = 0; mi < 4; mi++)
                ldsm_x4(af[mi],
                    a_base + ((wm + 16 * mi + lrow) * 36 + ks + lcol) * 4);
#pragma unroll
            for (int ni = 0; ni < 4; ni++) {
                bf[ni][0] = Bs[ks + i4][wn + 8 * ni + g];
                bf[ni][1] = Bs[ks + i4 + 4][wn + 8 * ni + g];
            }
#pragma unroll
            for (int mi = 0; mi < 4; mi++)
#pragma unroll
                for (int ni = 0; ni < 4; ni++)
                    mma_tf32(acc[mi][ni], af[mi], bf[ni]);
        }
        __syncthreads();
    }

#pragma unroll
    for (int mi = 0; mi < 4; mi++) {
#pragma unroll
        for (int ni = 0; ni < 4; ni++) {
#pragma unroll
            for (int e = 0; e < 4; e++) {
                int r = bm + wm + 16 * mi + g + (e >> 1) * 8;
                int n = bn + wn + 8 * ni + 2 * i4 + (e & 1);
                if (n < NPOS) g_R[(size_t)r * NPOS + n] = acc[mi][ni][e];
            }
        }
    }
}

// ===== S = (Q K^T + gather(R)) * 0.125 * pad  +  per-tile softmax stats =====
__global__ void __launch_bounds__(256) attn_scores_t(const float* __restrict__ pad)
{
    __shared__ __align__(16) unsigned Qs[128][36];
    __shared__ __align__(16) unsigned Ks[128][36];
    int z = blockIdx.z;
    const float* Qp = g_Q + (size_t)z * LSEQ * DH;
    const float* Kp = g_K + (size_t)z * LSEQ * DH;
    int bm = blockIdx.y * 128, bn = blockIdx.x * 128;
    int tid = threadIdx.x;
    int warp = tid >> 5, lane = tid & 31;
    int wm = (warp >> 2) * 64, wn = (warp & 3) * 32;
    int g = lane >> 2, i4 = lane & 3;

    // A-frag ldmatrix mapping
    int lrow = (lane & 7) + 8 * ((lane >> 3) & 1);
    int lcol = 4 * (lane >> 4);
    // B-frag ldmatrix mapping ([n][k] layout): blks (n0 k0, n0 k4, n8 k0, n8 k4)
    int brow = (lane & 7) + 8 * (lane >> 4);
    int bcol = 4 * ((lane >> 3) & 1);
    uint32_t q_base = (uint32_t)__cvta_generic_to_shared(&Qs[0][0]);
    uint32_t k_base = (uint32_t)__cvta_generic_to_shared(&Ks[0][0]);

    float acc[4][4][4] = {};
    int am = tid >> 3, ak = (tid & 7) * 4;

    for (int k0 = 0; k0 < DH; k0 += 32) {
#pragma unroll
        for (int r = 0; r < 4; r++) {
            float4 v = *(const float4*)&Qp[(size_t)(bm + am + 32 * r) * DH + k0 + ak];
            *(uint4*)&Qs[am + 32 * r][ak] =
                make_uint4(f2tf(v.x), f2tf(v.y), f2tf(v.z), f2tf(v.w));
            float4 w = *(const float4*)&Kp[(size_t)(bn + am + 32 * r) * DH + k0 + ak];
            *(uint4*)&Ks[am + 32 * r][ak] =
                make_uint4(f2tf(w.x), f2tf(w.y), f2tf(w.z), f2tf(w.w));
        }
        __syncthreads();
#pragma unroll
        for (int ks = 0; ks < 32; ks += 8) {
            unsigned af[4][4], bfr[2][4];
#pragma unroll
            for (int mi = 0; mi < 4; mi++)
                ldsm_x4(af[mi],
                    q_base + ((wm + 16 * mi + lrow) * 36 + ks + lcol) * 4);
#pragma unroll
            for (int p = 0; p < 2; p++)
                ldsm_x4(bfr[p],
                    k_base + ((wn + 16 * p + brow) * 36 + ks + bcol) * 4);
#pragma unroll
            for (int mi = 0; mi < 4; mi++)
#pragma unroll
                for (int ni = 0; ni < 4; ni++)
                    mma_tf32(acc[mi][ni], af[mi], &bfr[ni >> 1][(ni & 1) * 2]);
        }
        __syncthreads();
    }

    int b = z >> 4;
    int warp4 = warp & 3;
    float* smax = (float*)&Qs[0][0];   // 128*16
    float* ssum = smax + 2048;         // 128*16
    float* rowm = ssum + 2048;         // 128   (4224 floats <= 4608 avail)

    // pass 1: write raw S, per-thread row max
#pragma unroll
    for (int mi = 0; mi < 4; mi++) {
#pragma unroll
        for (int e1 = 0; e1 < 2; e1++) {
            int rl = wm + 16 * mi + g + 8 * e1;
            int q = bm + rl;
            float mx = -3.0e38f;
#pragma unroll
            for (int ni = 0; ni < 4; ni++) {
#pragma unroll
                for (int e0 = 0; e0 < 2; e0++) {
                    int kp = bn + wn + 8 * ni + 2 * i4 + e0;
                    int dlt = min(max(kp - q, -128), 128);
                    float r2 = g_R[((size_t)z * LSEQ + q) * NPOS + dlt + 128];
                    float s = (acc[mi][ni][e1 * 2 + e0] + r2) * 0.125f * pad[b * LSEQ + kp];
                    g_S[((size_t)z * LSEQ + q) * LSEQ + kp] = s;
                    acc[mi][ni][e1 * 2 + e0] = s;
                    mx = fmaxf(mx, s);
                }
            }
            smax[rl * 16 + warp4 * 4 + i4] = mx;
        }
    }
    __syncthreads();
    if (tid < 128) {
        float m = smax[tid * 16];
#pragma unroll
        for (int j = 1; j < 16; j++) m = fmaxf(m, smax[tid * 16 + j]);
        rowm[tid] = m;
    }
    __syncthreads();
#pragma unroll
    for (int mi = 0; mi < 4; mi++) {
#pragma unroll
        for (int e1 = 0; e1 < 2; e1++) {
            int rl = wm + 16 * mi + g + 8 * e1;
            float m = rowm[rl];
            float se = 0.f;
#pragma unroll
            for (int ni = 0; ni < 4; ni++)
#pragma unroll
                for (int e0 = 0; e0 < 2; e0++)
                    se += __expf(acc[mi][ni][e1 * 2 + e0] - m);
            ssum[rl * 16 + warp4 * 4 + i4] = se;
        }
    }
    __syncthreads();
    if (tid < 128) {
        float l = 0.f;
#pragma unroll
        for (int j = 0; j < 16; j++) l += ssum[tid * 16 + j];
        int q = bm + tid;
        g_stat[((size_t)z * LSEQ + q) * 8 + blockIdx.x] = make_float2(rowm[tid], l);
    }
}

// ====== combine per-tile stats -> per-row (max, 1/l) ========================
__global__ void __launch_bounds__(256) combine_stats()
{
    int row = blockIdx.x * 256 + threadIdx.x;
    const float2* st = &g_stat[(size_t)row * 8];
    float m = st[0].x;
#pragma unroll
    for (int j = 1; j < 8; j++) m = fmaxf(m, st[j].x);
    float l = 0.f;
#pragma unroll
    for (int j = 0; j < 8; j++) l += st[j].y * __expf(st[j].x - m);
    g_stat2[row] = make_float2(m, 1.f / l);
}

// ====== stats_T: p = exp(s-m)*il from raw S; write T only ===================
__global__ void __launch_bounds__(256) stats_T()
{
    int row = blockIdx.x;
    int q = row & 1023;
    const float* S = g_S + (size_t)row * LSEQ;
    float* T = g_T + (size_t)row * TP;
    int tid = threadIdx.x;
    int warp = tid >> 5, lane = tid & 31;
    __shared__ float sA[1024];
    __shared__ float r0s[8], r1s[8];

    float2 st = g_stat2[row];
    float m = st.x, il = st.y;

    float4 v = *(const float4*)&S[tid * 4];
    float p0 = __expf(v.x - m) * il;
    float p1 = __expf(v.y - m) * il;
    float p2 = __expf(v.z - m) * il;
    float p3 = __expf(v.w - m) * il;
    *(float4*)&sA[tid * 4] = make_float4(p0, p1, p2, p3);

    float s0 = 0.f, s1 = 0.f;
    int kb = tid * 4;
    int lo = q - 128, hi = q + 128;
    if (kb + 0 <= lo) s0 += p0; else if (kb + 0 >= hi) s1 += p0;
    if (kb + 1 <= lo) s0 += p1; else if (kb + 1 >= hi) s1 += p1;
    if (kb + 2 <= lo) s0 += p2; else if (kb + 2 >= hi) s1 += p2;
    if (kb + 3 <= lo) s0 += p3; else if (kb + 3 >= hi) s1 += p3;
#pragma unroll
    for (int off = 16; off > 0; off >>= 1) {
        s0 += __shfl_xor_sync(0xffffffffu, s0, off);
        s1 += __shfl_xor_sync(0xffffffffu, s1, off);
    }
    if (lane == 0) { r0s[warp] = s0; r1s[warp] = s1; }
    __syncthreads();

    if (tid < 255) {
        int p = tid + 1;
        int k = q + p - 128;
        T[p] = (k >= 0 && k < 1024) ? sA[k] : 0.f;
    }
    if (tid == 0) {
        float a0 = 0.f, a1 = 0.f;
#pragma unroll
        for (int j = 0; j < 8; j++) { a0 += r0s[j]; a1 += r1s[j]; }
        T[0] = a0; T[256] = a1;
    }
    if (tid >= 225 && tid < 225 + (TP - NPOS)) T[NPOS + (tid - 225)] = 0.f;
}

// ====== O1 = P @ V : P computed on the fly from raw S + stats ===============
__global__ void __launch_bounds__(256) gemm_av_t()
{
    __shared__ __align__(16) unsigned As[128][36];
    __shared__ __align__(16) unsigned Bs[32][72];
    __shared__ float rs[256];
    int z = blockIdx.y;
    const float* S = g_S + (size_t)z * LSEQ * LSEQ;
    const float* V = g_V + (size_t)z * LSEQ * DH;
    int bm = blockIdx.x * 128;
    int tid = threadIdx.x;
    int warp = tid >> 5, lane = tid & 31;
    int wm = (warp >> 1) * 32, wn = (warp & 1) * 32;
    int g = lane >> 2, i4 = lane & 3;

    int lrow = (lane & 7) + 8 * ((lane >> 3) & 1);
    int lcol = 4 * (lane >> 4);
    uint32_t a_base = (uint32_t)__cvta_generic_to_shared(&As[0][0]);

    if (tid < 128) {
        float2 st = g_stat2[(size_t)z * LSEQ + bm + tid];
        rs[tid * 2] = st.x;
        rs[tid * 2 + 1] = st.y;
    }
    __syncthreads();

    float acc[2][4][4] = {};
    int am = tid >> 3, ak = (tid & 7) * 4;
    int vk = tid >> 4, vn4 = (tid & 15) * 4;

    float4 ra[4], rv[2];
#pragma unroll
    for (int r = 0; r < 4; r++)
        ra[r] = *(const float4*)&S[(size_t)(bm + am + 32 * r) * LSEQ + ak];
#pragma unroll
    for (int r = 0; r < 2; r++)
        rv[r] = *(const float4*)&V[(size_t)(vk + 16 * r) * DH + vn4];

    for (int k0 = 0; k0 < LSEQ; k0 += 32) {
#pragma unroll
        for (int r = 0; r < 4; r++) {
            int rl = am + 32 * r;
            float m = rs[2 * rl], il = rs[2 * rl + 1];
            *(uint4*)&As[rl][ak] = make_uint4(
                f2tf(__expf(ra[r].x - m) * il),
                f2tf(__expf(ra[r].y - m) * il),
                f2tf(__expf(ra[r].z - m) * il),
                f2tf(__expf(ra[r].w - m) * il));
        }
#pragma unroll
        for (int r = 0; r < 2; r++)
            *(uint4*)&Bs[vk + 16 * r][vn4] =
                make_uint4(f2tf(rv[r].x), f2tf(rv[r].y), f2tf(rv[r].z), f2tf(rv[r].w));
        __syncthreads();
        if (k0 + 32 < LSEQ) {
#pragma unroll
            for (int r = 0; r < 4; r++)
                ra[r] = *(const float4*)&S[(size_t)(bm + am + 32 * r) * LSEQ + k0 + 32 + ak];
#pragma unroll
            for (int r = 0; r < 2; r++)
                rv[r] = *(const float4*)&V[(size_t)(k0 + 32 + vk + 16 * r) * DH + vn4];
        }
#pragma unroll
        for (int ks = 0; ks < 32; ks += 8) {
            unsigned af[2][4], bf[4][2];
#pragma unroll
            for (int mi = 0; mi < 2; mi++)
                ldsm_x4(af[mi],
                    a_base + ((wm + 16 * mi + lrow) * 36 + ks + lcol) * 4);
#pragma unroll
            for (int ni = 0; ni < 4; ni++) {
                bf[ni][0] = Bs[ks + i4][wn + 8 * ni + g];
                bf[ni][1] = Bs[ks + i4 + 4][wn + 8 * ni + g];
            }
#pragma unroll
            for (int mi = 0; mi < 2; mi++)
#pragma unroll
                for (int ni = 0; ni < 4; ni++)
                    mma_tf32(acc[mi][ni], af[mi], bf[ni]);
        }
        __syncthreads();
    }

    int b = z >> 4, h = z & 15;
#pragma unroll
    for (int mi = 0; mi < 2; mi++) {
#pragma unroll
        for (int ni = 0; ni < 4; ni++) {
#pragma unroll
            for (int e = 0; e < 4; e++) {
                int q = bm + wm + 16 * mi + g + (e >> 1) * 8;
                int n = wn + 8 * ni + 2 * i4 + (e & 1);
                g_O[((size_t)(b * LSEQ + q)) * DMODEL + h * 64 + n] = acc[mi][ni][e];
            }
        }
    }
}

// ====== g_O += T @ posV (tf32 mma; M=65536, N=64, K=288 padded) ============
__global__ void __launch_bounds__(256) gemm_tposv_t(const float* __restrict__ posV)
{
    __shared__ __align__(16) unsigned As[128][36];
    __shared__ __align__(16) unsigned Bs[32][72];
    int bm = blockIdx.x * 128;
    int tid = threadIdx.x;
    int warp = tid >> 5, lane = tid & 31;
    int wm = warp * 16;
    int g = lane >> 2, i4 = lane & 3;

    int lrow = (lane & 7) + 8 * ((lane >> 3) & 1);
    int lcol = 4 * (lane >> 4);
    uint32_t a_base = (uint32_t)__cvta_generic_to_shared(&As[0][0]);

    float acc[8][4] = {};
    int am = tid >> 3, ak = (tid & 7) * 4;
    int vk = tid >> 4, vn4 = (tid & 15) * 4;

    for (int k0 = 0; k0 < TP; k0 += 32) {
#pragma unroll
        for (int r = 0; r < 4; r++) {
            float4 v = *(const float4*)&g_T[(size_t)(bm + am + 32 * r) * TP + k0 + ak];
            *(uint4*)&As[am + 32 * r][ak] =
                make_uint4(f2tf(v.x), f2tf(v.y), f2tf(v.z), f2tf(v.w));
        }
#pragma unroll
        for (int r = 0; r < 2; r++) {
            int k = k0 + vk + 16 * r;
            float4 w = make_float4(0.f, 0.f, 0.f, 0.f);
            if (k < NPOS) w = *(const float4*)&posV[(size_t)k * DH + vn4];
            *(uint4*)&Bs[vk + 16 * r][vn4] =
                make_uint4(f2tf(w.x), f2tf(w.y), f2tf(w.z), f2tf(w.w));
        }
        __syncthreads();
#pragma unroll
        for (int ks = 0; ks < 32; ks += 8) {
            unsigned af[4], bf[8][2];
            ldsm_x4(af, a_base + ((wm + lrow) * 36 + ks + lcol) * 4);
#pragma unroll
            for (int ni = 0; ni < 8; ni++) {
                bf[ni][0] = Bs[ks + i4][8 * ni + g];
                bf[ni][1] = Bs[ks + i4 + 4][8 * ni + g];
            }
#pragma unroll
            for (int ni = 0; ni < 8; ni++)
                mma_tf32(acc[ni], af, bf[ni]);
        }
        __syncthreads();
    }

#pragma unroll
    for (int ni = 0; ni < 8; ni++) {
#pragma unroll
        for (int e = 0; e < 4; e++) {
            int r = bm + wm + g + (e >> 1) * 8;
            int z = r >> 10, q = r & 1023;
            int b = z >> 4, h = z & 15;
            int n = 8 * ni + 2 * i4 + (e & 1);
            size_t idx = ((size_t)(b * LSEQ + q)) * DMODEL + h * 64 + n;
            g_O[idx] += acc[ni][e];
        }
    }
}

// ---------------------------------------------------------------------------
extern "C" void kernel_launch(void* const* d_in, const int* in_sizes, int n_in,
                              void* d_out, int out_size)
{
    const float* x    = (const float*)d_in[0];
    const float* pad  = (const float*)d_in[1];
    const float* Wq   = (const float*)d_in[2];
    const float* bq   = (const float*)d_in[3];
    const float* Wk   = (const float*)d_in[4];
    const float* bk   = (const float*)d_in[5];
    const float* Wv   = (const float*)d_in[6];
    const float* bv   = (const float*)d_in[7];
    const float* Wo   = (const float*)d_in[8];
    const float* bo   = (const float*)d_in[9];
    const float* posK = (const float*)d_in[10];
    const float* posV = (const float*)d_in[11];
    float* out = (float*)d_out;

    gemm_qkv<<<dim3(DMODEL / 128, MROW / 128, 3), 256>>>(x, Wq, bq, Wk, bk, Wv, bv);
    gemm_qposk_t<<<dim3(3, ROWS / 128), 256>>>(posK);
    attn_scores_t<<<dim3(8, 8, BH), 256>>>(pad);
    combine_stats<<<ROWS / 256, 256>>>();
    stats_T<<<ROWS, 256>>>();
    gemm_av_t<<<dim3(8, BH), 256>>>();
    gemm_tposv_t<<<dim3(ROWS / 128), 256>>>(posV);
    gemm_out<<<dim3(DMODEL / 128, MROW / 128), 256>>>(Wo, bo, out);
}